// round 14
// baseline (speedup 1.0000x reference)
#include <cuda_runtime.h>
#include <cuda_fp16.h>
#include <cstdint>

// Problem constants
#define BB 4
#define TT 2048
#define DD 1024
#define HH 16
#define HD 64
#define DFF 4096
#define NROWS (BB * TT)          // 8192
#define EPS 1e-5f

// ---------------------------------------------------------------------------
// Scratch arena
// ---------------------------------------------------------------------------
#define SEG ((size_t)NROWS * DD)
#define MW  ((size_t)1024 * 1024)
#define OFF_H   ((size_t)0)
#define OFF_Q   (SEG * 1)
#define OFF_K   (SEG * 2)
#define OFF_V   (SEG * 3)
#define OFF_CTX (SEG * 4)
#define OFF_X2  (SEG * 5)
#define OFF_FF  (SEG * 6)
#define OFF_WC  (SEG * 6 + (size_t)NROWS * DFF)
#define OFF_WQKV (OFF_WC + MW * 0)           // packed fp16 [3072][1024]
#define OFF_WOC  (OFF_WC + MW * 3)
#define OFF_W1C  (OFF_WC + MW * 4)
#define OFF_W2C  (OFF_WC + MW * 8)
#define SCRATCH_FLOATS (OFF_WC + MW * 12)

__device__ __align__(256) float g_scratch[SCRATCH_FLOATS];

__device__ __forceinline__ const float* rsrc(const float* p, size_t off) {
    return p ? p : (const float*)(g_scratch + off);
}

__device__ __forceinline__ void cpa16(void* s, const void* g) {
    unsigned sp = (unsigned)__cvta_generic_to_shared(s);
    asm volatile("cp.async.cg.shared.global [%0], [%1], 16;\n" :: "r"(sp), "l"(g));
}
__device__ __forceinline__ void cpa_commit() { asm volatile("cp.async.commit_group;\n"); }
__device__ __forceinline__ void cpa_wait0()  { asm volatile("cp.async.wait_group 0;\n"); }
__device__ __forceinline__ void cpa_wait1()  { asm volatile("cp.async.wait_group 1;\n"); }
__device__ __forceinline__ void cpa_wait2()  { asm volatile("cp.async.wait_group 2;\n"); }
__device__ __forceinline__ void cpa_wait3()  { asm volatile("cp.async.wait_group 3;\n"); }

__device__ __forceinline__ void mma_f16(float* c, const unsigned* a, const unsigned* b) {
    asm volatile(
        "mma.sync.aligned.m16n8k16.row.col.f32.f16.f16.f32 "
        "{%0,%1,%2,%3}, {%4,%5,%6,%7}, {%8,%9}, {%0,%1,%2,%3};\n"
        : "+f"(c[0]), "+f"(c[1]), "+f"(c[2]), "+f"(c[3])
        : "r"(a[0]), "r"(a[1]), "r"(a[2]), "r"(a[3]), "r"(b[0]), "r"(b[1]));
}
__device__ __forceinline__ void ldsm_x4(unsigned& r0, unsigned& r1,
                                        unsigned& r2, unsigned& r3,
                                        const void* p) {
    unsigned addr = (unsigned)__cvta_generic_to_shared(p);
    asm volatile("ldmatrix.sync.aligned.m8n8.x4.shared.b16 {%0,%1,%2,%3}, [%4];"
                 : "=r"(r0), "=r"(r1), "=r"(r2), "=r"(r3) : "r"(addr));
}
__device__ __forceinline__ void ldsm_x4_trans(unsigned& r0, unsigned& r1,
                                              unsigned& r2, unsigned& r3,
                                              const void* p) {
    unsigned addr = (unsigned)__cvta_generic_to_shared(p);
    asm volatile("ldmatrix.sync.aligned.m8n8.x4.trans.shared.b16 {%0,%1,%2,%3}, [%4];"
                 : "=r"(r0), "=r"(r1), "=r"(r2), "=r"(r3) : "r"(addr));
}
__device__ __forceinline__ unsigned h2u(__half2 h) { return *(unsigned*)&h; }

// ---------------------------------------------------------------------------
// Fused weight transposes (one launch), unchanged from R13
// ---------------------------------------------------------------------------
__global__ void __launch_bounds__(256) trans_all_kernel(
    const float* __restrict__ wq, const float* __restrict__ wk,
    const float* __restrict__ wv, const float* __restrict__ wo,
    const float* __restrict__ w1, const float* __restrict__ w2)
{
    __shared__ float tile[32][33];
    const int bi = blockIdx.x;
    const float* src; __half* dst; int NS, K, n0, k0;
    if (bi < 3072) {
        const int m    = bi >> 10;
        const int r    = bi & 1023;
        const int head = r >> 6;
        const int tt   = r & 63;
        src = (m == 0 ? wq : (m == 1 ? wk : wv)) + (size_t)head * 1024 * 64;
        dst = (__half*)(g_scratch + OFF_WQKV) + m * MW + (size_t)head * 64 * 1024;
        NS = 64; K = 1024; n0 = (tt & 1) * 32; k0 = (tt >> 1) * 32;
    } else if (bi < 4096) {
        const int t = bi - 3072;
        src = wo; dst = (__half*)(g_scratch + OFF_WOC);
        NS = 1024; K = 1024; n0 = (t & 31) * 32; k0 = (t >> 5) * 32;
    } else if (bi < 8192) {
        const int t = bi - 4096;
        src = w1; dst = (__half*)(g_scratch + OFF_W1C);
        NS = 4096; K = 1024; n0 = (t & 127) * 32; k0 = (t >> 7) * 32;
    } else {
        const int t = bi - 8192;
        src = w2; dst = (__half*)(g_scratch + OFF_W2C);
        NS = 1024; K = 4096; n0 = (t & 31) * 32; k0 = (t >> 5) * 32;
    }
    const int tx = threadIdx.x, ty = threadIdx.y;
    #pragma unroll
    for (int i = 0; i < 32; i += 8)
        tile[ty + i][tx] = src[(size_t)(k0 + ty + i) * NS + n0 + tx];
    __syncthreads();
    #pragma unroll
    for (int i = 0; i < 32; i += 8)
        dst[(size_t)(n0 + ty + i) * K + k0 + tx] = __float2half_rn(tile[tx][ty + i]);
}

// ---------------------------------------------------------------------------
// LayerNorm: fp32 in -> fp16 out (unchanged)
// ---------------------------------------------------------------------------
__global__ void __launch_bounds__(256) ln_kernel(
    const float* __restrict__ xext, size_t xoff,
    const float* __restrict__ g, const float* __restrict__ be, size_t ooff)
{
    const float* x = rsrc(xext, xoff);
    __half* out = (__half*)(g_scratch + ooff);

    const int row = blockIdx.x;
    const int t   = threadIdx.x;
    const float4* xr = (const float4*)(x + (size_t)row * DD);
    float4 v = xr[t];

    float s = v.x + v.y + v.z + v.w;
    float q = v.x*v.x + v.y*v.y + v.z*v.z + v.w*v.w;
    #pragma unroll
    for (int o = 16; o; o >>= 1) {
        s += __shfl_xor_sync(0xffffffffu, s, o);
        q += __shfl_xor_sync(0xffffffffu, q, o);
    }
    __shared__ float ss[8], sq[8];
    if ((t & 31) == 0) { ss[t >> 5] = s; sq[t >> 5] = q; }
    __syncthreads();
    s = 0.f; q = 0.f;
    #pragma unroll
    for (int i = 0; i < 8; i++) { s += ss[i]; q += sq[i]; }

    const float mean = s * (1.0f / DD);
    const float var  = q * (1.0f / DD) - mean * mean;
    const float r    = rsqrtf(var + EPS);

    float4 gv = ((const float4*)g)[t];
    float4 bv = ((const float4*)be)[t];
    __half2 h0 = __floats2half2_rn((v.x - mean) * r * gv.x + bv.x,
                                   (v.y - mean) * r * gv.y + bv.y);
    __half2 h1 = __floats2half2_rn((v.z - mean) * r * gv.z + bv.z,
                                   (v.w - mean) * r * gv.w + bv.w);
    uint2 o; o.x = h2u(h0); o.y = h2u(h1);
    *(uint2*)(out + (size_t)row * DD + t * 4) = o;
}

// ---------------------------------------------------------------------------
// FP16 tensor-core GEMM: 128x128x32 CTA, 64x32 warp, ldmatrix fragments,
// 5-stage circular cp.async pipeline (100KB -> 2 CTAs/SM).
// ---------------------------------------------------------------------------
#define STG_H  ((size_t)(128 * 40 * 2))          // halves per stage (A+B)
#define HG_SMEM (5 * STG_H * 2)                  // bytes = 102400

template<bool BIAS, bool RELU, bool RESID, bool OUTH, bool SPLITN>
__global__ void __launch_bounds__(256, 2) hgemm_kernel(
    size_t aoff, size_t boff,
    const float* __restrict__ bias,
    const float* __restrict__ resid_ext, size_t resid_off,
    float* __restrict__ Cext, size_t coff,
    int M, int N, int K)
{
    extern __shared__ __half dsm[];
    const __half* A  = (const __half*)(g_scratch + aoff);
    const __half* Bt = (const __half*)(g_scratch + boff);
    const float* R = RESID ? rsrc(resid_ext, resid_off) : (const float*)nullptr;

    const int tid  = threadIdx.x;
    const int wid  = tid >> 5;
    const int lane = tid & 31;
    const int m0 = blockIdx.y * 128;
    const int n0 = blockIdx.x * 128;
    const int warp_m = (wid >> 2) * 64;
    const int warp_n = (wid & 3) * 32;
    const int g = lane >> 2;
    const int t = lane & 3;

    const int lm_row = (lane & 7) + ((lane >> 3) & 1) * 8;
    const int lm_col = (lane >> 4) * 8;
    const int lb_row = ((lane >> 4) * 8) + (lane & 7);
    const int lb_col = ((lane >> 3) & 1) * 8;

    float acc[4][4][4];
    #pragma unroll
    for (int mt = 0; mt < 4; mt++)
        #pragma unroll
        for (int nt = 0; nt < 4; nt++)
            #pragma unroll
            for (int r = 0; r < 4; r++) acc[mt][nt][r] = 0.f;

    const int nst = K >> 5;

    auto load_stage = [&](int s) {
        __half* sA = dsm + (size_t)(s % 5) * STG_H;
        __half* sB = sA + 128 * 40;
        const size_t kof = (size_t)s * 32;
        #pragma unroll
        for (int i = 0; i < 2; i++) {
            const int idx = tid + i * 256;
            const int r = idx >> 2;
            const int c = (idx & 3) << 3;
            cpa16(sA + r * 40 + c, A  + (size_t)(m0 + r) * K + kof + c);
            cpa16(sB + r * 40 + c, Bt + (size_t)(n0 + r) * K + kof + c);
        }
        cpa_commit();
    };

    load_stage(0);
    load_stage(1);
    load_stage(2);
    load_stage(3);

    for (int s = 0; s < nst; s++) {
        const int rem = nst - 1 - s;
        if (rem >= 3)      cpa_wait3();
        else if (rem == 2) cpa_wait2();
        else if (rem == 1) cpa_wait1();
        else               cpa_wait0();
        __syncthreads();
        const __half* sA = dsm + (size_t)(s % 5) * STG_H;
        const __half* sB = sA + 128 * 40;

        #pragma unroll
        for (int ks = 0; ks < 2; ks++) {
            unsigned af[4][4], bf[4][2];
            #pragma unroll
            for (int mt = 0; mt < 4; mt++)
                ldsm_x4(af[mt][0], af[mt][1], af[mt][2], af[mt][3],
                        sA + (warp_m + mt * 16 + lm_row) * 40 + ks * 16 + lm_col);
            #pragma unroll
            for (int np = 0; np < 2; np++)
                ldsm_x4(bf[2*np][0], bf[2*np][1], bf[2*np+1][0], bf[2*np+1][1],
                        sB + (warp_n + np * 16 + lb_row) * 40 + ks * 16 + lb_col);
            #pragma unroll
            for (int mt = 0; mt < 4; mt++)
                #pragma unroll
                for (int nt = 0; nt < 4; nt++)
                    mma_f16(acc[mt][nt], af[mt], bf[nt]);
        }

        if (s + 4 < nst) load_stage(s + 4);
    }

    #pragma unroll
    for (int mt = 0; mt < 4; mt++) {
        #pragma unroll
        for (int half_ = 0; half_ < 2; half_++) {
            const int gr = m0 + warp_m + mt * 16 + g + half_ * 8;
            const float* Rrow = RESID ? (R + (size_t)gr * N) : (const float*)nullptr;
            #pragma unroll
            for (int nt = 0; nt < 4; nt++) {
                const int gc = n0 + warp_n + nt * 8 + 2 * t;
                float v0 = acc[mt][nt][half_ * 2 + 0];
                float v1 = acc[mt][nt][half_ * 2 + 1];
                if (BIAS)  { v0 += bias[gc]; v1 += bias[gc + 1]; }
                if (RESID) { v0 += Rrow[gc]; v1 += Rrow[gc + 1]; }
                if (RELU)  { v0 = fmaxf(v0, 0.f); v1 = fmaxf(v1, 0.f); }
                if (SPLITN) {
                    __half* dst = (__half*)(g_scratch + coff + (size_t)(gc >> 10) * SEG);
                    *(__half2*)(dst + (size_t)gr * 1024 + (gc & 1023)) = __floats2half2_rn(v0, v1);
                } else if (OUTH) {
                    __half* Crow = (__half*)(g_scratch + coff) + (size_t)gr * N;
                    *(__half2*)(Crow + gc) = __floats2half2_rn(v0, v1);
                } else {
                    float* Crow = (Cext ? Cext : (g_scratch + coff)) + (size_t)gr * N;
                    *(float2*)(Crow + gc) = make_float2(v0, v1);
                }
            }
        }
    }
}

// ---------------------------------------------------------------------------
// FP16 tensor-core causal flash attention: 128-query x 64-key tiles.
// Grid: (T/128, H, B), qt reversed (LPT). Block: 256 threads = 8 warps,
// each warp owns 16 q rows. Double-buffered K/V, P in registers.
// ---------------------------------------------------------------------------
__global__ void __launch_bounds__(256) attn_kernel()
{
    __shared__ __half Ks[2][64][72];
    __shared__ __half Vs[2][64][72];

    const __half* qh = (const __half*)(g_scratch + OFF_Q);
    const __half* kh = (const __half*)(g_scratch + OFF_K);
    const __half* vh = (const __half*)(g_scratch + OFF_V);
    __half* ctx      = (__half*)(g_scratch + OFF_CTX);

    const int qt   = (int)(gridDim.x - 1) - (int)blockIdx.x;   // reversed
    const int head = blockIdx.y;
    const int b    = blockIdx.z;
    const int tid  = threadIdx.x;
    const int w    = tid >> 5;          // 0..7
    const int lane = tid & 31;
    const int g    = lane >> 2;
    const int t    = lane & 3;

    const int lb_row = ((lane >> 4) * 8) + (lane & 7);
    const int lb_col = ((lane >> 3) & 1) * 8;

    const int q0 = qt * 128;
    const size_t headoff = (size_t)head * 64;
    const size_t rowbase = (size_t)b * TT;

    auto issueKV = [&](int kt2, int bf) {
        const size_t kbase = (rowbase + (size_t)kt2 * 64) * DD + headoff;
        #pragma unroll
        for (int j = 0; j < 2; j++) {
            const int idx = tid + j * 256;     // 0..511
            const int row = idx >> 3;          // 0..63
            const int c   = (idx & 7) << 3;
            cpa16(&Ks[bf][row][c], kh + kbase + (size_t)row * DD + c);
            cpa16(&Vs[bf][row][c], vh + kbase + (size_t)row * DD + c);
        }
        cpa_commit();
    };

    issueKV(0, 0);

    // Q fragments straight from global (scaled by 1/8, exact in fp16)
    unsigned Qf[4][4];
    {
        const __half2 sc = __floats2half2_rn(0.125f, 0.125f);
        const size_t r0 = (rowbase + q0 + 16*w + g) * DD + headoff;
        const size_t r1 = r0 + 8 * DD;
        #pragma unroll
        for (int ks = 0; ks < 4; ks++) {
            const int e = ks * 16 + 2 * t;
            __half2 a0 = *(const __half2*)(qh + r0 + e);
            __half2 a1 = *(const __half2*)(qh + r1 + e);
            __half2 a2 = *(const __half2*)(qh + r0 + e + 8);
            __half2 a3 = *(const __half2*)(qh + r1 + e + 8);
            Qf[ks][0] = h2u(__hmul2(a0, sc));
            Qf[ks][1] = h2u(__hmul2(a1, sc));
            Qf[ks][2] = h2u(__hmul2(a2, sc));
            Qf[ks][3] = h2u(__hmul2(a3, sc));
        }
    }

    float Oacc[8][4];
    #pragma unroll
    for (int nt = 0; nt < 8; nt++)
        #pragma unroll
        for (int r = 0; r < 4; r++) Oacc[nt][r] = 0.f;
    float m0 = -1e30f, m1 = -1e30f, l0 = 0.f, l1 = 0.f;

    const int nkt = 2 * qt + 2;     // 64-key tiles covering q0+128 keys

    for (int kt = 0; kt < nkt; kt++) {
        const int buf = kt & 1;
        cpa_wait0();
        __syncthreads();
        if (kt + 1 < nkt) issueKV(kt + 1, buf ^ 1);

        // ---- S = Q K^T (16 x 64 per warp) ----
        float S[8][4];
        #pragma unroll
        for (int nt = 0; nt < 8; nt++)
            #pragma unroll
            for (int r = 0; r < 4; r++) S[nt][r] = 0.f;

        #pragma unroll
        for (int ks = 0; ks < 4; ks++) {
            unsigned bfrag[8][2];
            #pragma unroll
            for (int np = 0; np < 4; np++) {
                ldsm_x4(bfrag[2*np][0], bfrag[2*np][1], bfrag[2*np+1][0], bfrag[2*np+1][1],
                        &Ks[buf][np * 16 + lb_row][ks * 16 + lb_col]);
            }
            #pragma unroll
            for (int nt = 0; nt < 8; nt++)
                mma_f16(S[nt], Qf[ks], bfrag[nt]);
        }

        // ---- mask + online softmax ----
        const int qrow0 = q0 + 16*w + g;
        const int qrow1 = qrow0 + 8;
        if (kt >= 2 * qt) {          // tiles overlapping the diagonal band
            const int ktbase = kt * 64;
            #pragma unroll
            for (int nt = 0; nt < 8; nt++) {
                const int key = ktbase + nt*8 + 2*t;
                if (key     > qrow0) S[nt][0] = -1e30f;
                if (key + 1 > qrow0) S[nt][1] = -1e30f;
                if (key     > qrow1) S[nt][2] = -1e30f;
                if (key + 1 > qrow1) S[nt][3] = -1e30f;
            }
        }
        float mn0 = m0, mn1 = m1;
        #pragma unroll
        for (int nt = 0; nt < 8; nt++) {
            mn0 = fmaxf(mn0, fmaxf(S[nt][0], S[nt][1]));
            mn1 = fmaxf(mn1, fmaxf(S[nt][2], S[nt][3]));
        }
        mn0 = fmaxf(mn0, __shfl_xor_sync(0xffffffffu, mn0, 1));
        mn0 = fmaxf(mn0, __shfl_xor_sync(0xffffffffu, mn0, 2));
        mn1 = fmaxf(mn1, __shfl_xor_sync(0xffffffffu, mn1, 1));
        mn1 = fmaxf(mn1, __shfl_xor_sync(0xffffffffu, mn1, 2));

        const float corr0 = __expf(m0 - mn0);
        const float corr1 = __expf(m1 - mn1);
        m0 = mn0; m1 = mn1;

        // P in registers: S fragment layout == PV A fragment layout
        unsigned Pa[8][2];
        float ls0 = 0.f, ls1 = 0.f;
        #pragma unroll
        for (int nt = 0; nt < 8; nt++) {
            __half2 p0 = __floats2half2_rn(__expf(S[nt][0] - m0), __expf(S[nt][1] - m0));
            __half2 p1 = __floats2half2_rn(__expf(S[nt][2] - m1), __expf(S[nt][3] - m1));
            Pa[nt][0] = h2u(p0);
            Pa[nt][1] = h2u(p1);
            const float2 f0 = __half22float2(p0);
            const float2 f1 = __half22float2(p1);
            ls0 += f0.x + f0.y;
            ls1 += f1.x + f1.y;
        }
        ls0 += __shfl_xor_sync(0xffffffffu, ls0, 1);
        ls0 += __shfl_xor_sync(0xffffffffu, ls0, 2);
        ls1 += __shfl_xor_sync(0xffffffffu, ls1, 1);
        ls1 += __shfl_xor_sync(0xffffffffu, ls1, 2);
        l0 = l0 * corr0 + ls0;
        l1 = l1 * corr1 + ls1;

        #pragma unroll
        for (int nt = 0; nt < 8; nt++) {
            Oacc[nt][0] *= corr0; Oacc[nt][1] *= corr0;
            Oacc[nt][2] *= corr1; Oacc[nt][3] *= corr1;
        }

        // ---- O += P V (16 x 64 per warp, k=64) ----
        #pragma unroll
        for (int ks = 0; ks < 4; ks++) {
            unsigned af[4];
            af[0] = Pa[2*ks    ][0];
            af[1] = Pa[2*ks    ][1];
            af[2] = Pa[2*ks + 1][0];
            af[3] = Pa[2*ks + 1][1];
            #pragma unroll
            for (int np = 0; np < 4; np++) {
                const int vrow = ks * 16 + (lane & 7) + ((lane >> 3) & 1) * 8;
                const int vcol = 8 * (2 * np + (lane >> 4));
                unsigned b0, b1, b2, b3;
                ldsm_x4_trans(b0, b1, b2, b3, &Vs[buf][vrow][vcol]);
                unsigned bf0[2] = {b0, b1};
                unsigned bf1[2] = {b2, b3};
                mma_f16(Oacc[2*np    ], af, bf0);
                mma_f16(Oacc[2*np + 1], af, bf1);
            }
        }
    }

    // ---- epilogue: normalize + store fp16 ctx ----
    const float inv0 = 1.f / l0;
    const float inv1 = 1.f / l1;
    __half* base0 = ctx + (rowbase + q0 + 16*w + g    ) * DD + headoff;
    __half* base1 = ctx + (rowbase + q0 + 16*w + g + 8) * DD + headoff;
    #pragma unroll
    for (int nt = 0; nt < 8; nt++) {
        const int col = nt*8 + 2*t;
        *(__half2*)(base0 + col) = __floats2half2_rn(Oacc[nt][0] * inv0, Oacc[nt][1] * inv0);
        *(__half2*)(base1 + col) = __floats2half2_rn(Oacc[nt][2] * inv1, Oacc[nt][3] * inv1);
    }
}

// ---------------------------------------------------------------------------
// Launch
// ---------------------------------------------------------------------------
extern "C" void kernel_launch(void* const* d_in, const int* in_sizes, int n_in,
                              void* d_out, int out_size)
{
    const float* x   = (const float*)d_in[0];
    const float* Wq  = (const float*)d_in[1];
    const float* Wk  = (const float*)d_in[2];
    const float* Wv  = (const float*)d_in[3];
    const float* Wo  = (const float*)d_in[4];
    const float* bo  = (const float*)d_in[5];
    const float* W1  = (const float*)d_in[6];
    const float* b1  = (const float*)d_in[7];
    const float* W2  = (const float*)d_in[8];
    const float* b2  = (const float*)d_in[9];
    const float* g1  = (const float*)d_in[10];
    const float* be1 = (const float*)d_in[11];
    const float* g2  = (const float*)d_in[12];
    const float* be2 = (const float*)d_in[13];
    float* out = (float*)d_out;

    // Opt-in dynamic SMEM
    cudaFuncSetAttribute(hgemm_kernel<false,false,false,true,true>,
                         cudaFuncAttributeMaxDynamicSharedMemorySize, HG_SMEM);
    cudaFuncSetAttribute(hgemm_kernel<true,false,true,false,false>,
                         cudaFuncAttributeMaxDynamicSharedMemorySize, HG_SMEM);
    cudaFuncSetAttribute(hgemm_kernel<true,true,false,true,false>,
                         cudaFuncAttributeMaxDynamicSharedMemorySize, HG_SMEM);

    // 0) ALL weight transposes in one launch
    trans_all_kernel<<<12288, dim3(32, 8)>>>(Wq, Wk, Wv, Wo, W1, W2);

    // 1) LN1: x -> h (fp16)
    ln_kernel<<<NROWS, 256>>>(x, 0, g1, be1, OFF_H);

    // 2) Fused QKV projection (N = 3072; outputs split into q/k/v fp16)
    hgemm_kernel<false,false,false,true,true>
        <<<dim3(3072/128, NROWS/128), 256, HG_SMEM>>>(
        OFF_H, OFF_WQKV, nullptr, nullptr, 0, nullptr, OFF_Q, NROWS, 3072, DD);

    // 3) FP16 tensor-core causal flash attention -> ctx (fp16)
    attn_kernel<<<dim3(TT / 128, HH, BB), 256>>>();

    // 4) Output projection + bias + residual(x): ctx -> x2 (fp32)
    dim3 gq(DD / 128, NROWS / 128);
    hgemm_kernel<true,false,true,false,false><<<gq, 256, HG_SMEM>>>(
        OFF_CTX, OFF_WOC, bo, x, 0, nullptr, OFF_X2, NROWS, DD, DD);

    // 5) LN2: x2 -> h (fp16)
    ln_kernel<<<NROWS, 256>>>(nullptr, OFF_X2, g2, be2, OFF_H);

    // 6) FFN1 (+bias, relu): h -> ff (fp16)
    hgemm_kernel<true,true,false,true,false>
        <<<dim3(DFF / 128, NROWS / 128), 256, HG_SMEM>>>(
        OFF_H, OFF_W1C, b1, nullptr, 0, nullptr, OFF_FF, NROWS, DFF, DD);

    // 7) FFN2 (+bias, +residual x2) -> final output (fp32)
    hgemm_kernel<true,false,true,false,false><<<gq, 256, HG_SMEM>>>(
        OFF_FF, OFF_W2C, b2, nullptr, OFF_X2, out, 0, NROWS, DD, DFF);
}

// round 15
// speedup vs baseline: 1.0409x; 1.0409x over previous
#include <cuda_runtime.h>
#include <cuda_fp16.h>
#include <cstdint>

// Problem constants
#define BB 4
#define TT 2048
#define DD 1024
#define HH 16
#define HD 64
#define DFF 4096
#define NROWS (BB * TT)          // 8192
#define EPS 1e-5f

// ---------------------------------------------------------------------------
// Scratch arena
// ---------------------------------------------------------------------------
#define SEG ((size_t)NROWS * DD)
#define MW  ((size_t)1024 * 1024)
#define OFF_H   ((size_t)0)
#define OFF_Q   (SEG * 1)
#define OFF_K   (SEG * 2)
#define OFF_V   (SEG * 3)
#define OFF_CTX (SEG * 4)
#define OFF_X2  (SEG * 5)
#define OFF_FF  (SEG * 6)
#define OFF_WC  (SEG * 6 + (size_t)NROWS * DFF)
#define OFF_WQKV (OFF_WC + MW * 0)           // packed fp16 [3072][1024]
#define OFF_WOC  (OFF_WC + MW * 3)
#define OFF_W1C  (OFF_WC + MW * 4)
#define OFF_W2C  (OFF_WC + MW * 8)
#define SCRATCH_FLOATS (OFF_WC + MW * 12)

__device__ __align__(256) float g_scratch[SCRATCH_FLOATS];

__device__ __forceinline__ const float* rsrc(const float* p, size_t off) {
    return p ? p : (const float*)(g_scratch + off);
}

__device__ __forceinline__ void cpa16(void* s, const void* g) {
    unsigned sp = (unsigned)__cvta_generic_to_shared(s);
    asm volatile("cp.async.cg.shared.global [%0], [%1], 16;\n" :: "r"(sp), "l"(g));
}
__device__ __forceinline__ void cpa_commit() { asm volatile("cp.async.commit_group;\n"); }
__device__ __forceinline__ void cpa_wait0()  { asm volatile("cp.async.wait_group 0;\n"); }
__device__ __forceinline__ void cpa_wait2()  { asm volatile("cp.async.wait_group 2;\n"); }

__device__ __forceinline__ void mma_f16(float* c, const unsigned* a, const unsigned* b) {
    asm volatile(
        "mma.sync.aligned.m16n8k16.row.col.f32.f16.f16.f32 "
        "{%0,%1,%2,%3}, {%4,%5,%6,%7}, {%8,%9}, {%0,%1,%2,%3};\n"
        : "+f"(c[0]), "+f"(c[1]), "+f"(c[2]), "+f"(c[3])
        : "r"(a[0]), "r"(a[1]), "r"(a[2]), "r"(a[3]), "r"(b[0]), "r"(b[1]));
}
__device__ __forceinline__ void ldsm_x4(unsigned& r0, unsigned& r1,
                                        unsigned& r2, unsigned& r3,
                                        const void* p) {
    unsigned addr = (unsigned)__cvta_generic_to_shared(p);
    asm volatile("ldmatrix.sync.aligned.m8n8.x4.shared.b16 {%0,%1,%2,%3}, [%4];"
                 : "=r"(r0), "=r"(r1), "=r"(r2), "=r"(r3) : "r"(addr));
}
__device__ __forceinline__ void ldsm_x4_trans(unsigned& r0, unsigned& r1,
                                              unsigned& r2, unsigned& r3,
                                              const void* p) {
    unsigned addr = (unsigned)__cvta_generic_to_shared(p);
    asm volatile("ldmatrix.sync.aligned.m8n8.x4.trans.shared.b16 {%0,%1,%2,%3}, [%4];"
                 : "=r"(r0), "=r"(r1), "=r"(r2), "=r"(r3) : "r"(addr));
}
__device__ __forceinline__ unsigned h2u(__half2 h) { return *(unsigned*)&h; }

// ---------------------------------------------------------------------------
// Fused weight transposes (one launch)
// ---------------------------------------------------------------------------
__global__ void __launch_bounds__(256) trans_all_kernel(
    const float* __restrict__ wq, const float* __restrict__ wk,
    const float* __restrict__ wv, const float* __restrict__ wo,
    const float* __restrict__ w1, const float* __restrict__ w2)
{
    __shared__ float tile[32][33];
    const int bi = blockIdx.x;
    const float* src; __half* dst; int NS, K, n0, k0;
    if (bi < 3072) {
        const int m    = bi >> 10;
        const int r    = bi & 1023;
        const int head = r >> 6;
        const int tt   = r & 63;
        src = (m == 0 ? wq : (m == 1 ? wk : wv)) + (size_t)head * 1024 * 64;
        dst = (__half*)(g_scratch + OFF_WQKV) + m * MW + (size_t)head * 64 * 1024;
        NS = 64; K = 1024; n0 = (tt & 1) * 32; k0 = (tt >> 1) * 32;
    } else if (bi < 4096) {
        const int t = bi - 3072;
        src = wo; dst = (__half*)(g_scratch + OFF_WOC);
        NS = 1024; K = 1024; n0 = (t & 31) * 32; k0 = (t >> 5) * 32;
    } else if (bi < 8192) {
        const int t = bi - 4096;
        src = w1; dst = (__half*)(g_scratch + OFF_W1C);
        NS = 4096; K = 1024; n0 = (t & 127) * 32; k0 = (t >> 7) * 32;
    } else {
        const int t = bi - 8192;
        src = w2; dst = (__half*)(g_scratch + OFF_W2C);
        NS = 1024; K = 4096; n0 = (t & 31) * 32; k0 = (t >> 5) * 32;
    }
    const int tx = threadIdx.x, ty = threadIdx.y;
    #pragma unroll
    for (int i = 0; i < 32; i += 8)
        tile[ty + i][tx] = src[(size_t)(k0 + ty + i) * NS + n0 + tx];
    __syncthreads();
    #pragma unroll
    for (int i = 0; i < 32; i += 8)
        dst[(size_t)(n0 + ty + i) * K + k0 + tx] = __float2half_rn(tile[tx][ty + i]);
}

// ---------------------------------------------------------------------------
// LayerNorm: fp32 in -> fp16 out
// ---------------------------------------------------------------------------
__global__ void __launch_bounds__(256) ln_kernel(
    const float* __restrict__ xext, size_t xoff,
    const float* __restrict__ g, const float* __restrict__ be, size_t ooff)
{
    const float* x = rsrc(xext, xoff);
    __half* out = (__half*)(g_scratch + ooff);

    const int row = blockIdx.x;
    const int t   = threadIdx.x;
    const float4* xr = (const float4*)(x + (size_t)row * DD);
    float4 v = xr[t];

    float s = v.x + v.y + v.z + v.w;
    float q = v.x*v.x + v.y*v.y + v.z*v.z + v.w*v.w;
    #pragma unroll
    for (int o = 16; o; o >>= 1) {
        s += __shfl_xor_sync(0xffffffffu, s, o);
        q += __shfl_xor_sync(0xffffffffu, q, o);
    }
    __shared__ float ss[8], sq[8];
    if ((t & 31) == 0) { ss[t >> 5] = s; sq[t >> 5] = q; }
    __syncthreads();
    s = 0.f; q = 0.f;
    #pragma unroll
    for (int i = 0; i < 8; i++) { s += ss[i]; q += sq[i]; }

    const float mean = s * (1.0f / DD);
    const float var  = q * (1.0f / DD) - mean * mean;
    const float r    = rsqrtf(var + EPS);

    float4 gv = ((const float4*)g)[t];
    float4 bv = ((const float4*)be)[t];
    __half2 h0 = __floats2half2_rn((v.x - mean) * r * gv.x + bv.x,
                                   (v.y - mean) * r * gv.y + bv.y);
    __half2 h1 = __floats2half2_rn((v.z - mean) * r * gv.z + bv.z,
                                   (v.w - mean) * r * gv.w + bv.w);
    uint2 o; o.x = h2u(h0); o.y = h2u(h1);
    *(uint2*)(out + (size_t)row * DD + t * 4) = o;
}

// ---------------------------------------------------------------------------
// FP16 tensor-core GEMM (R12/R13 proven config): 128x128x32 CTA, 64x32 warp,
// 4-stage circular cp.async pipeline (80KB -> 2 CTAs/SM), ldmatrix fragments.
// ---------------------------------------------------------------------------
#define STG_H  ((size_t)(128 * 40 * 2))          // halves per stage (A+B)
#define HG_SMEM (4 * STG_H * 2)                  // bytes = 81920

template<bool BIAS, bool RELU, bool RESID, bool OUTH, bool SPLITN>
__global__ void __launch_bounds__(256, 2) hgemm_kernel(
    size_t aoff, size_t boff,
    const float* __restrict__ bias,
    const float* __restrict__ resid_ext, size_t resid_off,
    float* __restrict__ Cext, size_t coff,
    int M, int N, int K)
{
    extern __shared__ __half dsm[];
    const __half* A  = (const __half*)(g_scratch + aoff);
    const __half* Bt = (const __half*)(g_scratch + boff);
    const float* R = RESID ? rsrc(resid_ext, resid_off) : (const float*)nullptr;

    const int tid  = threadIdx.x;
    const int wid  = tid >> 5;
    const int lane = tid & 31;
    const int m0 = blockIdx.y * 128;
    const int n0 = blockIdx.x * 128;
    const int warp_m = (wid >> 2) * 64;
    const int warp_n = (wid & 3) * 32;
    const int g = lane >> 2;
    const int t = lane & 3;

    const int lm_row = (lane & 7) + ((lane >> 3) & 1) * 8;
    const int lm_col = (lane >> 4) * 8;
    const int lb_row = ((lane >> 4) * 8) + (lane & 7);
    const int lb_col = ((lane >> 3) & 1) * 8;

    float acc[4][4][4];
    #pragma unroll
    for (int mt = 0; mt < 4; mt++)
        #pragma unroll
        for (int nt = 0; nt < 4; nt++)
            #pragma unroll
            for (int r = 0; r < 4; r++) acc[mt][nt][r] = 0.f;

    const int nst = K >> 5;

    auto load_stage = [&](int s) {
        __half* sA = dsm + (size_t)(s & 3) * STG_H;
        __half* sB = sA + 128 * 40;
        const size_t kof = (size_t)s * 32;
        #pragma unroll
        for (int i = 0; i < 2; i++) {
            const int idx = tid + i * 256;
            const int r = idx >> 2;
            const int c = (idx & 3) << 3;
            cpa16(sA + r * 40 + c, A  + (size_t)(m0 + r) * K + kof + c);
            cpa16(sB + r * 40 + c, Bt + (size_t)(n0 + r) * K + kof + c);
        }
        cpa_commit();
    };

    load_stage(0);
    load_stage(1);
    load_stage(2);

    for (int s = 0; s < nst; s++) {
        if (s + 2 < nst) cpa_wait2(); else cpa_wait0();
        __syncthreads();
        const __half* sA = dsm + (size_t)(s & 3) * STG_H;
        const __half* sB = sA + 128 * 40;

        #pragma unroll
        for (int ks = 0; ks < 2; ks++) {
            unsigned af[4][4], bf[4][2];
            #pragma unroll
            for (int mt = 0; mt < 4; mt++)
                ldsm_x4(af[mt][0], af[mt][1], af[mt][2], af[mt][3],
                        sA + (warp_m + mt * 16 + lm_row) * 40 + ks * 16 + lm_col);
            #pragma unroll
            for (int np = 0; np < 2; np++)
                ldsm_x4(bf[2*np][0], bf[2*np][1], bf[2*np+1][0], bf[2*np+1][1],
                        sB + (warp_n + np * 16 + lb_row) * 40 + ks * 16 + lb_col);
            #pragma unroll
            for (int mt = 0; mt < 4; mt++)
                #pragma unroll
                for (int nt = 0; nt < 4; nt++)
                    mma_f16(acc[mt][nt], af[mt], bf[nt]);
        }

        if (s + 3 < nst) load_stage(s + 3);
    }

    #pragma unroll
    for (int mt = 0; mt < 4; mt++) {
        #pragma unroll
        for (int half_ = 0; half_ < 2; half_++) {
            const int gr = m0 + warp_m + mt * 16 + g + half_ * 8;
            const float* Rrow = RESID ? (R + (size_t)gr * N) : (const float*)nullptr;
            #pragma unroll
            for (int nt = 0; nt < 4; nt++) {
                const int gc = n0 + warp_n + nt * 8 + 2 * t;
                float v0 = acc[mt][nt][half_ * 2 + 0];
                float v1 = acc[mt][nt][half_ * 2 + 1];
                if (BIAS)  { v0 += bias[gc]; v1 += bias[gc + 1]; }
                if (RESID) { v0 += Rrow[gc]; v1 += Rrow[gc + 1]; }
                if (RELU)  { v0 = fmaxf(v0, 0.f); v1 = fmaxf(v1, 0.f); }
                if (SPLITN) {
                    __half* dst = (__half*)(g_scratch + coff + (size_t)(gc >> 10) * SEG);
                    *(__half2*)(dst + (size_t)gr * 1024 + (gc & 1023)) = __floats2half2_rn(v0, v1);
                } else if (OUTH) {
                    __half* Crow = (__half*)(g_scratch + coff) + (size_t)gr * N;
                    *(__half2*)(Crow + gc) = __floats2half2_rn(v0, v1);
                } else {
                    float* Crow = (Cext ? Cext : (g_scratch + coff)) + (size_t)gr * N;
                    *(float2*)(Crow + gc) = make_float2(v0, v1);
                }
            }
        }
    }
}

// ---------------------------------------------------------------------------
// FP16 tensor-core causal flash attention: 64-query x 64-key tiles (R13
// proven config). Grid: (T/64, H, B), qt reversed (LPT). Block: 128 threads.
// Softmax l-sum accumulates fp32 exp directly (no half round-trip).
// ---------------------------------------------------------------------------
__global__ void __launch_bounds__(128) attn_kernel()
{
    __shared__ __half Ks[2][64][72];
    __shared__ __half Vs[2][64][72];

    const __half* qh = (const __half*)(g_scratch + OFF_Q);
    const __half* kh = (const __half*)(g_scratch + OFF_K);
    const __half* vh = (const __half*)(g_scratch + OFF_V);
    __half* ctx      = (__half*)(g_scratch + OFF_CTX);

    const int qt   = (int)(gridDim.x - 1) - (int)blockIdx.x;   // reversed
    const int head = blockIdx.y;
    const int b    = blockIdx.z;
    const int tid  = threadIdx.x;
    const int w    = tid >> 5;
    const int lane = tid & 31;
    const int g    = lane >> 2;
    const int t    = lane & 3;

    const int lb_row = ((lane >> 4) * 8) + (lane & 7);
    const int lb_col = ((lane >> 3) & 1) * 8;

    const int q0 = qt * 64;
    const size_t headoff = (size_t)head * 64;
    const size_t rowbase = (size_t)b * TT;

    auto issueKV = [&](int kt2, int bf) {
        const size_t kbase = (rowbase + (size_t)kt2 * 64) * DD + headoff;
        #pragma unroll
        for (int j = 0; j < 4; j++) {
            const int idx = tid + j * 128;
            const int row = idx >> 3;
            const int c   = (idx & 7) << 3;
            cpa16(&Ks[bf][row][c], kh + kbase + (size_t)row * DD + c);
            cpa16(&Vs[bf][row][c], vh + kbase + (size_t)row * DD + c);
        }
        cpa_commit();
    };

    issueKV(0, 0);

    unsigned Qf[4][4];
    {
        const __half2 sc = __floats2half2_rn(0.125f, 0.125f);
        const size_t r0 = (rowbase + q0 + 16*w + g) * DD + headoff;
        const size_t r1 = r0 + 8 * DD;
        #pragma unroll
        for (int ks = 0; ks < 4; ks++) {
            const int e = ks * 16 + 2 * t;
            __half2 a0 = *(const __half2*)(qh + r0 + e);
            __half2 a1 = *(const __half2*)(qh + r1 + e);
            __half2 a2 = *(const __half2*)(qh + r0 + e + 8);
            __half2 a3 = *(const __half2*)(qh + r1 + e + 8);
            Qf[ks][0] = h2u(__hmul2(a0, sc));
            Qf[ks][1] = h2u(__hmul2(a1, sc));
            Qf[ks][2] = h2u(__hmul2(a2, sc));
            Qf[ks][3] = h2u(__hmul2(a3, sc));
        }
    }

    float Oacc[8][4];
    #pragma unroll
    for (int nt = 0; nt < 8; nt++)
        #pragma unroll
        for (int r = 0; r < 4; r++) Oacc[nt][r] = 0.f;
    float m0 = -1e30f, m1 = -1e30f, l0 = 0.f, l1 = 0.f;

    const int nkt = qt + 1;

    for (int kt = 0; kt < nkt; kt++) {
        const int buf = kt & 1;
        cpa_wait0();
        __syncthreads();
        if (kt + 1 < nkt) issueKV(kt + 1, buf ^ 1);

        // ---- S = Q K^T (64 x 64) ----
        float S[8][4];
        #pragma unroll
        for (int nt = 0; nt < 8; nt++)
            #pragma unroll
            for (int r = 0; r < 4; r++) S[nt][r] = 0.f;

        #pragma unroll
        for (int ks = 0; ks < 4; ks++) {
            unsigned bfrag[8][2];
            #pragma unroll
            for (int np = 0; np < 4; np++) {
                ldsm_x4(bfrag[2*np][0], bfrag[2*np][1], bfrag[2*np+1][0], bfrag[2*np+1][1],
                        &Ks[buf][np * 16 + lb_row][ks * 16 + lb_col]);
            }
            #pragma unroll
            for (int nt = 0; nt < 8; nt++)
                mma_f16(S[nt], Qf[ks], bfrag[nt]);
        }

        // ---- mask + online softmax ----
        const int qrow0 = q0 + 16*w + g;
        const int qrow1 = qrow0 + 8;
        if (kt == qt) {
            const int ktbase = kt * 64;
            #pragma unroll
            for (int nt = 0; nt < 8; nt++) {
                const int key = ktbase + nt*8 + 2*t;
                if (key     > qrow0) S[nt][0] = -1e30f;
                if (key + 1 > qrow0) S[nt][1] = -1e30f;
                if (key     > qrow1) S[nt][2] = -1e30f;
                if (key + 1 > qrow1) S[nt][3] = -1e30f;
            }
        }
        float mn0 = m0, mn1 = m1;
        #pragma unroll
        for (int nt = 0; nt < 8; nt++) {
            mn0 = fmaxf(mn0, fmaxf(S[nt][0], S[nt][1]));
            mn1 = fmaxf(mn1, fmaxf(S[nt][2], S[nt][3]));
        }
        mn0 = fmaxf(mn0, __shfl_xor_sync(0xffffffffu, mn0, 1));
        mn0 = fmaxf(mn0, __shfl_xor_sync(0xffffffffu, mn0, 2));
        mn1 = fmaxf(mn1, __shfl_xor_sync(0xffffffffu, mn1, 1));
        mn1 = fmaxf(mn1, __shfl_xor_sync(0xffffffffu, mn1, 2));

        const float corr0 = __expf(m0 - mn0);
        const float corr1 = __expf(m1 - mn1);
        m0 = mn0; m1 = mn1;

        // P in registers; l-sum from fp32 exps directly
        unsigned Pa[8][2];
        float ls0 = 0.f, ls1 = 0.f;
        #pragma unroll
        for (int nt = 0; nt < 8; nt++) {
            float e0 = __expf(S[nt][0] - m0);
            float e1 = __expf(S[nt][1] - m0);
            float e2 = __expf(S[nt][2] - m1);
            float e3 = __expf(S[nt][3] - m1);
            ls0 += e0 + e1;
            ls1 += e2 + e3;
            Pa[nt][0] = h2u(__floats2half2_rn(e0, e1));
            Pa[nt][1] = h2u(__floats2half2_rn(e2, e3));
        }
        ls0 += __shfl_xor_sync(0xffffffffu, ls0, 1);
        ls0 += __shfl_xor_sync(0xffffffffu, ls0, 2);
        ls1 += __shfl_xor_sync(0xffffffffu, ls1, 1);
        ls1 += __shfl_xor_sync(0xffffffffu, ls1, 2);
        l0 = l0 * corr0 + ls0;
        l1 = l1 * corr1 + ls1;

        #pragma unroll
        for (int nt = 0; nt < 8; nt++) {
            Oacc[nt][0] *= corr0; Oacc[nt][1] *= corr0;
            Oacc[nt][2] *= corr1; Oacc[nt][3] *= corr1;
        }

        // ---- O += P V (64 x 64, k=64) ----
        #pragma unroll
        for (int ks = 0; ks < 4; ks++) {
            unsigned af[4];
            af[0] = Pa[2*ks    ][0];
            af[1] = Pa[2*ks    ][1];
            af[2] = Pa[2*ks + 1][0];
            af[3] = Pa[2*ks + 1][1];
            #pragma unroll
            for (int np = 0; np < 4; np++) {
                const int vrow = ks * 16 + (lane & 7) + ((lane >> 3) & 1) * 8;
                const int vcol = 8 * (2 * np + (lane >> 4));
                unsigned b0, b1, b2, b3;
                ldsm_x4_trans(b0, b1, b2, b3, &Vs[buf][vrow][vcol]);
                unsigned bf0[2] = {b0, b1};
                unsigned bf1[2] = {b2, b3};
                mma_f16(Oacc[2*np    ], af, bf0);
                mma_f16(Oacc[2*np + 1], af, bf1);
            }
        }
    }

    // ---- epilogue: normalize + store fp16 ctx ----
    const float inv0 = 1.f / l0;
    const float inv1 = 1.f / l1;
    __half* base0 = ctx + (rowbase + q0 + 16*w + g    ) * DD + headoff;
    __half* base1 = ctx + (rowbase + q0 + 16*w + g + 8) * DD + headoff;
    #pragma unroll
    for (int nt = 0; nt < 8; nt++) {
        const int col = nt*8 + 2*t;
        *(__half2*)(base0 + col) = __floats2half2_rn(Oacc[nt][0] * inv0, Oacc[nt][1] * inv0);
        *(__half2*)(base1 + col) = __floats2half2_rn(Oacc[nt][2] * inv1, Oacc[nt][3] * inv1);
    }
}

// ---------------------------------------------------------------------------
// Launch
// ---------------------------------------------------------------------------
extern "C" void kernel_launch(void* const* d_in, const int* in_sizes, int n_in,
                              void* d_out, int out_size)
{
    const float* x   = (const float*)d_in[0];
    const float* Wq  = (const float*)d_in[1];
    const float* Wk  = (const float*)d_in[2];
    const float* Wv  = (const float*)d_in[3];
    const float* Wo  = (const float*)d_in[4];
    const float* bo  = (const float*)d_in[5];
    const float* W1  = (const float*)d_in[6];
    const float* b1  = (const float*)d_in[7];
    const float* W2  = (const float*)d_in[8];
    const float* b2  = (const float*)d_in[9];
    const float* g1  = (const float*)d_in[10];
    const float* be1 = (const float*)d_in[11];
    const float* g2  = (const float*)d_in[12];
    const float* be2 = (const float*)d_in[13];
    float* out = (float*)d_out;

    // Opt-in dynamic SMEM
    cudaFuncSetAttribute(hgemm_kernel<false,false,false,true,true>,
                         cudaFuncAttributeMaxDynamicSharedMemorySize, HG_SMEM);
    cudaFuncSetAttribute(hgemm_kernel<true,false,true,false,false>,
                         cudaFuncAttributeMaxDynamicSharedMemorySize, HG_SMEM);
    cudaFuncSetAttribute(hgemm_kernel<true,true,false,true,false>,
                         cudaFuncAttributeMaxDynamicSharedMemorySize, HG_SMEM);

    // 0) ALL weight transposes in one launch
    trans_all_kernel<<<12288, dim3(32, 8)>>>(Wq, Wk, Wv, Wo, W1, W2);

    // 1) LN1: x -> h (fp16)
    ln_kernel<<<NROWS, 256>>>(x, 0, g1, be1, OFF_H);

    // 2) Fused QKV projection (N = 3072; outputs split into q/k/v fp16)
    hgemm_kernel<false,false,false,true,true>
        <<<dim3(3072/128, NROWS/128), 256, HG_SMEM>>>(
        OFF_H, OFF_WQKV, nullptr, nullptr, 0, nullptr, OFF_Q, NROWS, 3072, DD);

    // 3) FP16 tensor-core causal flash attention -> ctx (fp16)
    attn_kernel<<<dim3(TT / 64, HH, BB), 128>>>();

    // 4) Output projection + bias + residual(x): ctx -> x2 (fp32)
    dim3 gq(DD / 128, NROWS / 128);
    hgemm_kernel<true,false,true,false,false><<<gq, 256, HG_SMEM>>>(
        OFF_CTX, OFF_WOC, bo, x, 0, nullptr, OFF_X2, NROWS, DD, DD);

    // 5) LN2: x2 -> h (fp16)
    ln_kernel<<<NROWS, 256>>>(nullptr, OFF_X2, g2, be2, OFF_H);

    // 6) FFN1 (+bias, relu): h -> ff (fp16)
    hgemm_kernel<true,true,false,true,false>
        <<<dim3(DFF / 128, NROWS / 128), 256, HG_SMEM>>>(
        OFF_H, OFF_W1C, b1, nullptr, 0, nullptr, OFF_FF, NROWS, DFF, DD);

    // 7) FFN2 (+bias, +residual x2) -> final output (fp32)
    hgemm_kernel<true,false,true,false,false><<<gq, 256, HG_SMEM>>>(
        OFF_FF, OFF_W2C, b2, nullptr, OFF_X2, out, 0, NROWS, DD, DFF);
}

// round 16
// speedup vs baseline: 1.6124x; 1.5491x over previous
#include <cuda_runtime.h>
#include <cuda_fp16.h>
#include <cstdint>

// Problem constants
#define BB 4
#define TT 2048
#define DD 1024
#define HH 16
#define HD 64
#define DFF 4096
#define NROWS (BB * TT)          // 8192
#define EPS 1e-5f

// ---------------------------------------------------------------------------
// Scratch arena
// ---------------------------------------------------------------------------
#define SEG ((size_t)NROWS * DD)
#define MW  ((size_t)1024 * 1024)
#define OFF_H   ((size_t)0)
#define OFF_Q   (SEG * 1)
#define OFF_K   (SEG * 2)
#define OFF_V   (SEG * 3)
#define OFF_CTX (SEG * 4)
#define OFF_X2  (SEG * 5)
#define OFF_FF  (SEG * 6)
#define OFF_WC  (SEG * 6 + (size_t)NROWS * DFF)
#define OFF_WQKV (OFF_WC + MW * 0)           // packed fp16 [3072][1024]
#define OFF_WOC  (OFF_WC + MW * 3)
#define OFF_W1C  (OFF_WC + MW * 4)
#define OFF_W2C  (OFF_WC + MW * 8)
#define SCRATCH_FLOATS (OFF_WC + MW * 12)

__device__ __align__(256) float g_scratch[SCRATCH_FLOATS];

__device__ __forceinline__ const float* rsrc(const float* p, size_t off) {
    return p ? p : (const float*)(g_scratch + off);
}

__device__ __forceinline__ void cpa16(void* s, const void* g) {
    unsigned sp = (unsigned)__cvta_generic_to_shared(s);
    asm volatile("cp.async.cg.shared.global [%0], [%1], 16;\n" :: "r"(sp), "l"(g));
}
__device__ __forceinline__ void cpa_commit() { asm volatile("cp.async.commit_group;\n"); }
__device__ __forceinline__ void cpa_wait0()  { asm volatile("cp.async.wait_group 0;\n"); }
__device__ __forceinline__ void cpa_wait2()  { asm volatile("cp.async.wait_group 2;\n"); }

__device__ __forceinline__ void mma_f16(float* c, const unsigned* a, const unsigned* b) {
    asm volatile(
        "mma.sync.aligned.m16n8k16.row.col.f32.f16.f16.f32 "
        "{%0,%1,%2,%3}, {%4,%5,%6,%7}, {%8,%9}, {%0,%1,%2,%3};\n"
        : "+f"(c[0]), "+f"(c[1]), "+f"(c[2]), "+f"(c[3])
        : "r"(a[0]), "r"(a[1]), "r"(a[2]), "r"(a[3]), "r"(b[0]), "r"(b[1]));
}
__device__ __forceinline__ void ldsm_x4(unsigned& r0, unsigned& r1,
                                        unsigned& r2, unsigned& r3,
                                        const void* p) {
    unsigned addr = (unsigned)__cvta_generic_to_shared(p);
    asm volatile("ldmatrix.sync.aligned.m8n8.x4.shared.b16 {%0,%1,%2,%3}, [%4];"
                 : "=r"(r0), "=r"(r1), "=r"(r2), "=r"(r3) : "r"(addr));
}
__device__ __forceinline__ void ldsm_x4_trans(unsigned& r0, unsigned& r1,
                                              unsigned& r2, unsigned& r3,
                                              const void* p) {
    unsigned addr = (unsigned)__cvta_generic_to_shared(p);
    asm volatile("ldmatrix.sync.aligned.m8n8.x4.trans.shared.b16 {%0,%1,%2,%3}, [%4];"
                 : "=r"(r0), "=r"(r1), "=r"(r2), "=r"(r3) : "r"(addr));
}
__device__ __forceinline__ unsigned h2u(__half2 h) { return *(unsigned*)&h; }

// ---------------------------------------------------------------------------
// Fused weight transposes (one launch)
// ---------------------------------------------------------------------------
__global__ void __launch_bounds__(256) trans_all_kernel(
    const float* __restrict__ wq, const float* __restrict__ wk,
    const float* __restrict__ wv, const float* __restrict__ wo,
    const float* __restrict__ w1, const float* __restrict__ w2)
{
    __shared__ float tile[32][33];
    const int bi = blockIdx.x;
    const float* src; __half* dst; int NS, K, n0, k0;
    if (bi < 3072) {
        const int m    = bi >> 10;
        const int r    = bi & 1023;
        const int head = r >> 6;
        const int tt   = r & 63;
        src = (m == 0 ? wq : (m == 1 ? wk : wv)) + (size_t)head * 1024 * 64;
        dst = (__half*)(g_scratch + OFF_WQKV) + m * MW + (size_t)head * 64 * 1024;
        NS = 64; K = 1024; n0 = (tt & 1) * 32; k0 = (tt >> 1) * 32;
    } else if (bi < 4096) {
        const int t = bi - 3072;
        src = wo; dst = (__half*)(g_scratch + OFF_WOC);
        NS = 1024; K = 1024; n0 = (t & 31) * 32; k0 = (t >> 5) * 32;
    } else if (bi < 8192) {
        const int t = bi - 4096;
        src = w1; dst = (__half*)(g_scratch + OFF_W1C);
        NS = 4096; K = 1024; n0 = (t & 127) * 32; k0 = (t >> 7) * 32;
    } else {
        const int t = bi - 8192;
        src = w2; dst = (__half*)(g_scratch + OFF_W2C);
        NS = 1024; K = 4096; n0 = (t & 31) * 32; k0 = (t >> 5) * 32;
    }
    const int tx = threadIdx.x, ty = threadIdx.y;
    #pragma unroll
    for (int i = 0; i < 32; i += 8)
        tile[ty + i][tx] = src[(size_t)(k0 + ty + i) * NS + n0 + tx];
    __syncthreads();
    #pragma unroll
    for (int i = 0; i < 32; i += 8)
        dst[(size_t)(n0 + ty + i) * K + k0 + tx] = __float2half_rn(tile[tx][ty + i]);
}

// ---------------------------------------------------------------------------
// LayerNorm: fp32 in -> fp16 out
// ---------------------------------------------------------------------------
__global__ void __launch_bounds__(256) ln_kernel(
    const float* __restrict__ xext, size_t xoff,
    const float* __restrict__ g, const float* __restrict__ be, size_t ooff)
{
    const float* x = rsrc(xext, xoff);
    __half* out = (__half*)(g_scratch + ooff);

    const int row = blockIdx.x;
    const int t   = threadIdx.x;
    const float4* xr = (const float4*)(x + (size_t)row * DD);
    float4 v = xr[t];

    float s = v.x + v.y + v.z + v.w;
    float q = v.x*v.x + v.y*v.y + v.z*v.z + v.w*v.w;
    #pragma unroll
    for (int o = 16; o; o >>= 1) {
        s += __shfl_xor_sync(0xffffffffu, s, o);
        q += __shfl_xor_sync(0xffffffffu, q, o);
    }
    __shared__ float ss[8], sq[8];
    if ((t & 31) == 0) { ss[t >> 5] = s; sq[t >> 5] = q; }
    __syncthreads();
    s = 0.f; q = 0.f;
    #pragma unroll
    for (int i = 0; i < 8; i++) { s += ss[i]; q += sq[i]; }

    const float mean = s * (1.0f / DD);
    const float var  = q * (1.0f / DD) - mean * mean;
    const float r    = rsqrtf(var + EPS);

    float4 gv = ((const float4*)g)[t];
    float4 bv = ((const float4*)be)[t];
    __half2 h0 = __floats2half2_rn((v.x - mean) * r * gv.x + bv.x,
                                   (v.y - mean) * r * gv.y + bv.y);
    __half2 h1 = __floats2half2_rn((v.z - mean) * r * gv.z + bv.z,
                                   (v.w - mean) * r * gv.w + bv.w);
    uint2 o; o.x = h2u(h0); o.y = h2u(h1);
    *(uint2*)(out + (size_t)row * DD + t * 4) = o;
}

// ---------------------------------------------------------------------------
// FP16 tensor-core GEMM (R12/R13 proven config): 128x128x32 CTA, 64x32 warp,
// 4-stage circular cp.async pipeline (80KB -> 2 CTAs/SM), ldmatrix fragments.
// ---------------------------------------------------------------------------
#define STG_H  ((size_t)(128 * 40 * 2))          // halves per stage (A+B)
#define HG_SMEM (4 * STG_H * 2)                  // bytes = 81920

template<bool BIAS, bool RELU, bool RESID, bool OUTH, bool SPLITN>
__global__ void __launch_bounds__(256, 2) hgemm_kernel(
    size_t aoff, size_t boff,
    const float* __restrict__ bias,
    const float* __restrict__ resid_ext, size_t resid_off,
    float* __restrict__ Cext, size_t coff,
    int M, int N, int K)
{
    extern __shared__ __half dsm[];
    const __half* A  = (const __half*)(g_scratch + aoff);
    const __half* Bt = (const __half*)(g_scratch + boff);
    const float* R = RESID ? rsrc(resid_ext, resid_off) : (const float*)nullptr;

    const int tid  = threadIdx.x;
    const int wid  = tid >> 5;
    const int lane = tid & 31;
    const int m0 = blockIdx.y * 128;
    const int n0 = blockIdx.x * 128;
    const int warp_m = (wid >> 2) * 64;
    const int warp_n = (wid & 3) * 32;
    const int g = lane >> 2;
    const int t = lane & 3;

    const int lm_row = (lane & 7) + ((lane >> 3) & 1) * 8;
    const int lm_col = (lane >> 4) * 8;
    const int lb_row = ((lane >> 4) * 8) + (lane & 7);
    const int lb_col = ((lane >> 3) & 1) * 8;

    float acc[4][4][4];
    #pragma unroll
    for (int mt = 0; mt < 4; mt++)
        #pragma unroll
        for (int nt = 0; nt < 4; nt++)
            #pragma unroll
            for (int r = 0; r < 4; r++) acc[mt][nt][r] = 0.f;

    const int nst = K >> 5;

    auto load_stage = [&](int s) {
        __half* sA = dsm + (size_t)(s & 3) * STG_H;
        __half* sB = sA + 128 * 40;
        const size_t kof = (size_t)s * 32;
        #pragma unroll
        for (int i = 0; i < 2; i++) {
            const int idx = tid + i * 256;
            const int r = idx >> 2;
            const int c = (idx & 3) << 3;
            cpa16(sA + r * 40 + c, A  + (size_t)(m0 + r) * K + kof + c);
            cpa16(sB + r * 40 + c, Bt + (size_t)(n0 + r) * K + kof + c);
        }
        cpa_commit();
    };

    load_stage(0);
    load_stage(1);
    load_stage(2);

    for (int s = 0; s < nst; s++) {
        if (s + 2 < nst) cpa_wait2(); else cpa_wait0();
        __syncthreads();
        const __half* sA = dsm + (size_t)(s & 3) * STG_H;
        const __half* sB = sA + 128 * 40;

        #pragma unroll
        for (int ks = 0; ks < 2; ks++) {
            unsigned af[4][4], bf[4][2];
            #pragma unroll
            for (int mt = 0; mt < 4; mt++)
                ldsm_x4(af[mt][0], af[mt][1], af[mt][2], af[mt][3],
                        sA + (warp_m + mt * 16 + lm_row) * 40 + ks * 16 + lm_col);
            #pragma unroll
            for (int np = 0; np < 2; np++)
                ldsm_x4(bf[2*np][0], bf[2*np][1], bf[2*np+1][0], bf[2*np+1][1],
                        sB + (warp_n + np * 16 + lb_row) * 40 + ks * 16 + lb_col);
            #pragma unroll
            for (int mt = 0; mt < 4; mt++)
                #pragma unroll
                for (int nt = 0; nt < 4; nt++)
                    mma_f16(acc[mt][nt], af[mt], bf[nt]);
        }

        if (s + 3 < nst) load_stage(s + 3);
    }

    #pragma unroll
    for (int mt = 0; mt < 4; mt++) {
        #pragma unroll
        for (int half_ = 0; half_ < 2; half_++) {
            const int gr = m0 + warp_m + mt * 16 + g + half_ * 8;
            const float* Rrow = RESID ? (R + (size_t)gr * N) : (const float*)nullptr;
            #pragma unroll
            for (int nt = 0; nt < 4; nt++) {
                const int gc = n0 + warp_n + nt * 8 + 2 * t;
                float v0 = acc[mt][nt][half_ * 2 + 0];
                float v1 = acc[mt][nt][half_ * 2 + 1];
                if (BIAS)  { v0 += bias[gc]; v1 += bias[gc + 1]; }
                if (RESID) { v0 += Rrow[gc]; v1 += Rrow[gc + 1]; }
                if (RELU)  { v0 = fmaxf(v0, 0.f); v1 = fmaxf(v1, 0.f); }
                if (SPLITN) {
                    __half* dst = (__half*)(g_scratch + coff + (size_t)(gc >> 10) * SEG);
                    *(__half2*)(dst + (size_t)gr * 1024 + (gc & 1023)) = __floats2half2_rn(v0, v1);
                } else if (OUTH) {
                    __half* Crow = (__half*)(g_scratch + coff) + (size_t)gr * N;
                    *(__half2*)(Crow + gc) = __floats2half2_rn(v0, v1);
                } else {
                    float* Crow = (Cext ? Cext : (g_scratch + coff)) + (size_t)gr * N;
                    *(float2*)(Crow + gc) = make_float2(v0, v1);
                }
            }
        }
    }
}

// ---------------------------------------------------------------------------
// FP16 tensor-core causal flash attention: 64-query x 64-key tiles (R13
// proven config). Grid: (T/64, H, B), qt reversed (LPT). Block: 128 threads.
// Softmax l-sum accumulates fp32 exp directly (no half round-trip).
// ---------------------------------------------------------------------------
__global__ void __launch_bounds__(128) attn_kernel()
{
    __shared__ __half Ks[2][64][72];
    __shared__ __half Vs[2][64][72];

    const __half* qh = (const __half*)(g_scratch + OFF_Q);
    const __half* kh = (const __half*)(g_scratch + OFF_K);
    const __half* vh = (const __half*)(g_scratch + OFF_V);
    __half* ctx      = (__half*)(g_scratch + OFF_CTX);

    const int qt   = (int)(gridDim.x - 1) - (int)blockIdx.x;   // reversed
    const int head = blockIdx.y;
    const int b    = blockIdx.z;
    const int tid  = threadIdx.x;
    const int w    = tid >> 5;
    const int lane = tid & 31;
    const int g    = lane >> 2;
    const int t    = lane & 3;

    const int lb_row = ((lane >> 4) * 8) + (lane & 7);
    const int lb_col = ((lane >> 3) & 1) * 8;

    const int q0 = qt * 64;
    const size_t headoff = (size_t)head * 64;
    const size_t rowbase = (size_t)b * TT;

    auto issueKV = [&](int kt2, int bf) {
        const size_t kbase = (rowbase + (size_t)kt2 * 64) * DD + headoff;
        #pragma unroll
        for (int j = 0; j < 4; j++) {
            const int idx = tid + j * 128;
            const int row = idx >> 3;
            const int c   = (idx & 7) << 3;
            cpa16(&Ks[bf][row][c], kh + kbase + (size_t)row * DD + c);
            cpa16(&Vs[bf][row][c], vh + kbase + (size_t)row * DD + c);
        }
        cpa_commit();
    };

    issueKV(0, 0);

    unsigned Qf[4][4];
    {
        const __half2 sc = __floats2half2_rn(0.125f, 0.125f);
        const size_t r0 = (rowbase + q0 + 16*w + g) * DD + headoff;
        const size_t r1 = r0 + 8 * DD;
        #pragma unroll
        for (int ks = 0; ks < 4; ks++) {
            const int e = ks * 16 + 2 * t;
            __half2 a0 = *(const __half2*)(qh + r0 + e);
            __half2 a1 = *(const __half2*)(qh + r1 + e);
            __half2 a2 = *(const __half2*)(qh + r0 + e + 8);
            __half2 a3 = *(const __half2*)(qh + r1 + e + 8);
            Qf[ks][0] = h2u(__hmul2(a0, sc));
            Qf[ks][1] = h2u(__hmul2(a1, sc));
            Qf[ks][2] = h2u(__hmul2(a2, sc));
            Qf[ks][3] = h2u(__hmul2(a3, sc));
        }
    }

    float Oacc[8][4];
    #pragma unroll
    for (int nt = 0; nt < 8; nt++)
        #pragma unroll
        for (int r = 0; r < 4; r++) Oacc[nt][r] = 0.f;
    float m0 = -1e30f, m1 = -1e30f, l0 = 0.f, l1 = 0.f;

    const int nkt = qt + 1;

    for (int kt = 0; kt < nkt; kt++) {
        const int buf = kt & 1;
        cpa_wait0();
        __syncthreads();
        if (kt + 1 < nkt) issueKV(kt + 1, buf ^ 1);

        // ---- S = Q K^T (64 x 64) ----
        float S[8][4];
        #pragma unroll
        for (int nt = 0; nt < 8; nt++)
            #pragma unroll
            for (int r = 0; r < 4; r++) S[nt][r] = 0.f;

        #pragma unroll
        for (int ks = 0; ks < 4; ks++) {
            unsigned bfrag[8][2];
            #pragma unroll
            for (int np = 0; np < 4; np++) {
                ldsm_x4(bfrag[2*np][0], bfrag[2*np][1], bfrag[2*np+1][0], bfrag[2*np+1][1],
                        &Ks[buf][np * 16 + lb_row][ks * 16 + lb_col]);
            }
            #pragma unroll
            for (int nt = 0; nt < 8; nt++)
                mma_f16(S[nt], Qf[ks], bfrag[nt]);
        }

        // ---- mask + online softmax ----
        const int qrow0 = q0 + 16*w + g;
        const int qrow1 = qrow0 + 8;
        if (kt == qt) {
            const int ktbase = kt * 64;
            #pragma unroll
            for (int nt = 0; nt < 8; nt++) {
                const int key = ktbase + nt*8 + 2*t;
                if (key     > qrow0) S[nt][0] = -1e30f;
                if (key + 1 > qrow0) S[nt][1] = -1e30f;
                if (key     > qrow1) S[nt][2] = -1e30f;
                if (key + 1 > qrow1) S[nt][3] = -1e30f;
            }
        }
        float mn0 = m0, mn1 = m1;
        #pragma unroll
        for (int nt = 0; nt < 8; nt++) {
            mn0 = fmaxf(mn0, fmaxf(S[nt][0], S[nt][1]));
            mn1 = fmaxf(mn1, fmaxf(S[nt][2], S[nt][3]));
        }
        mn0 = fmaxf(mn0, __shfl_xor_sync(0xffffffffu, mn0, 1));
        mn0 = fmaxf(mn0, __shfl_xor_sync(0xffffffffu, mn0, 2));
        mn1 = fmaxf(mn1, __shfl_xor_sync(0xffffffffu, mn1, 1));
        mn1 = fmaxf(mn1, __shfl_xor_sync(0xffffffffu, mn1, 2));

        const float corr0 = __expf(m0 - mn0);
        const float corr1 = __expf(m1 - mn1);
        m0 = mn0; m1 = mn1;

        // P in registers; l-sum from fp32 exps directly
        unsigned Pa[8][2];
        float ls0 = 0.f, ls1 = 0.f;
        #pragma unroll
        for (int nt = 0; nt < 8; nt++) {
            float e0 = __expf(S[nt][0] - m0);
            float e1 = __expf(S[nt][1] - m0);
            float e2 = __expf(S[nt][2] - m1);
            float e3 = __expf(S[nt][3] - m1);
            ls0 += e0 + e1;
            ls1 += e2 + e3;
            Pa[nt][0] = h2u(__floats2half2_rn(e0, e1));
            Pa[nt][1] = h2u(__floats2half2_rn(e2, e3));
        }
        ls0 += __shfl_xor_sync(0xffffffffu, ls0, 1);
        ls0 += __shfl_xor_sync(0xffffffffu, ls0, 2);
        ls1 += __shfl_xor_sync(0xffffffffu, ls1, 1);
        ls1 += __shfl_xor_sync(0xffffffffu, ls1, 2);
        l0 = l0 * corr0 + ls0;
        l1 = l1 * corr1 + ls1;

        #pragma unroll
        for (int nt = 0; nt < 8; nt++) {
            Oacc[nt][0] *= corr0; Oacc[nt][1] *= corr0;
            Oacc[nt][2] *= corr1; Oacc[nt][3] *= corr1;
        }

        // ---- O += P V (64 x 64, k=64) ----
        #pragma unroll
        for (int ks = 0; ks < 4; ks++) {
            unsigned af[4];
            af[0] = Pa[2*ks    ][0];
            af[1] = Pa[2*ks    ][1];
            af[2] = Pa[2*ks + 1][0];
            af[3] = Pa[2*ks + 1][1];
            #pragma unroll
            for (int np = 0; np < 4; np++) {
                const int vrow = ks * 16 + (lane & 7) + ((lane >> 3) & 1) * 8;
                const int vcol = 8 * (2 * np + (lane >> 4));
                unsigned b0, b1, b2, b3;
                ldsm_x4_trans(b0, b1, b2, b3, &Vs[buf][vrow][vcol]);
                unsigned bf0[2] = {b0, b1};
                unsigned bf1[2] = {b2, b3};
                mma_f16(Oacc[2*np    ], af, bf0);
                mma_f16(Oacc[2*np + 1], af, bf1);
            }
        }
    }

    // ---- epilogue: normalize + store fp16 ctx ----
    const float inv0 = 1.f / l0;
    const float inv1 = 1.f / l1;
    __half* base0 = ctx + (rowbase + q0 + 16*w + g    ) * DD + headoff;
    __half* base1 = ctx + (rowbase + q0 + 16*w + g + 8) * DD + headoff;
    #pragma unroll
    for (int nt = 0; nt < 8; nt++) {
        const int col = nt*8 + 2*t;
        *(__half2*)(base0 + col) = __floats2half2_rn(Oacc[nt][0] * inv0, Oacc[nt][1] * inv0);
        *(__half2*)(base1 + col) = __floats2half2_rn(Oacc[nt][2] * inv1, Oacc[nt][3] * inv1);
    }
}

// ---------------------------------------------------------------------------
// Launch
// ---------------------------------------------------------------------------
extern "C" void kernel_launch(void* const* d_in, const int* in_sizes, int n_in,
                              void* d_out, int out_size)
{
    const float* x   = (const float*)d_in[0];
    const float* Wq  = (const float*)d_in[1];
    const float* Wk  = (const float*)d_in[2];
    const float* Wv  = (const float*)d_in[3];
    const float* Wo  = (const float*)d_in[4];
    const float* bo  = (const float*)d_in[5];
    const float* W1  = (const float*)d_in[6];
    const float* b1  = (const float*)d_in[7];
    const float* W2  = (const float*)d_in[8];
    const float* b2  = (const float*)d_in[9];
    const float* g1  = (const float*)d_in[10];
    const float* be1 = (const float*)d_in[11];
    const float* g2  = (const float*)d_in[12];
    const float* be2 = (const float*)d_in[13];
    float* out = (float*)d_out;

    // Opt-in dynamic SMEM
    cudaFuncSetAttribute(hgemm_kernel<false,false,false,true,true>,
                         cudaFuncAttributeMaxDynamicSharedMemorySize, HG_SMEM);
    cudaFuncSetAttribute(hgemm_kernel<true,false,true,false,false>,
                         cudaFuncAttributeMaxDynamicSharedMemorySize, HG_SMEM);
    cudaFuncSetAttribute(hgemm_kernel<true,true,false,true,false>,
                         cudaFuncAttributeMaxDynamicSharedMemorySize, HG_SMEM);

    // 0) ALL weight transposes in one launch
    trans_all_kernel<<<12288, dim3(32, 8)>>>(Wq, Wk, Wv, Wo, W1, W2);

    // 1) LN1: x -> h (fp16)
    ln_kernel<<<NROWS, 256>>>(x, 0, g1, be1, OFF_H);

    // 2) Fused QKV projection (N = 3072; outputs split into q/k/v fp16)
    hgemm_kernel<false,false,false,true,true>
        <<<dim3(3072/128, NROWS/128), 256, HG_SMEM>>>(
        OFF_H, OFF_WQKV, nullptr, nullptr, 0, nullptr, OFF_Q, NROWS, 3072, DD);

    // 3) FP16 tensor-core causal flash attention -> ctx (fp16)
    attn_kernel<<<dim3(TT / 64, HH, BB), 128>>>();

    // 4) Output projection + bias + residual(x): ctx -> x2 (fp32)
    dim3 gq(DD / 128, NROWS / 128);
    hgemm_kernel<true,false,true,false,false><<<gq, 256, HG_SMEM>>>(
        OFF_CTX, OFF_WOC, bo, x, 0, nullptr, OFF_X2, NROWS, DD, DD);

    // 5) LN2: x2 -> h (fp16)
    ln_kernel<<<NROWS, 256>>>(nullptr, OFF_X2, g2, be2, OFF_H);

    // 6) FFN1 (+bias, relu): h -> ff (fp16)
    hgemm_kernel<true,true,false,true,false>
        <<<dim3(DFF / 128, NROWS / 128), 256, HG_SMEM>>>(
        OFF_H, OFF_W1C, b1, nullptr, 0, nullptr, OFF_FF, NROWS, DFF, DD);

    // 7) FFN2 (+bias, +residual x2) -> final output (fp32)
    hgemm_kernel<true,false,true,false,false><<<gq, 256, HG_SMEM>>>(
        OFF_FF, OFF_W2C, b2, nullptr, OFF_X2, out, 0, NROWS, DD, DFF);
}

// round 17
// speedup vs baseline: 1.6151x; 1.0016x over previous
#include <cuda_runtime.h>
#include <cuda_fp16.h>
#include <cstdint>

// Problem constants
#define BB 4
#define TT 2048
#define DD 1024
#define HH 16
#define HD 64
#define DFF 4096
#define NROWS (BB * TT)          // 8192
#define EPS 1e-5f

// ---------------------------------------------------------------------------
// Scratch arena
// ---------------------------------------------------------------------------
#define SEG ((size_t)NROWS * DD)
#define MW  ((size_t)1024 * 1024)
#define OFF_H   ((size_t)0)
#define OFF_Q   (SEG * 1)
#define OFF_K   (SEG * 2)
#define OFF_V   (SEG * 3)
#define OFF_CTX (SEG * 4)
#define OFF_X2  (SEG * 5)
#define OFF_FF  (SEG * 6)
#define OFF_WC  (SEG * 6 + (size_t)NROWS * DFF)
#define OFF_WQKV (OFF_WC + MW * 0)           // packed fp16 [3072][1024]
#define OFF_WOC  (OFF_WC + MW * 3)
#define OFF_W1C  (OFF_WC + MW * 4)
#define OFF_W2C  (OFF_WC + MW * 8)
#define SCRATCH_FLOATS (OFF_WC + MW * 12)

__device__ __align__(256) float g_scratch[SCRATCH_FLOATS];

__device__ __forceinline__ const float* rsrc(const float* p, size_t off) {
    return p ? p : (const float*)(g_scratch + off);
}

__device__ __forceinline__ void cpa16(void* s, const void* g) {
    unsigned sp = (unsigned)__cvta_generic_to_shared(s);
    asm volatile("cp.async.cg.shared.global [%0], [%1], 16;\n" :: "r"(sp), "l"(g));
}
__device__ __forceinline__ void cpa_commit() { asm volatile("cp.async.commit_group;\n"); }
__device__ __forceinline__ void cpa_wait0()  { asm volatile("cp.async.wait_group 0;\n"); }
__device__ __forceinline__ void cpa_wait2()  { asm volatile("cp.async.wait_group 2;\n"); }

__device__ __forceinline__ void mma_f16(float* c, const unsigned* a, const unsigned* b) {
    asm volatile(
        "mma.sync.aligned.m16n8k16.row.col.f32.f16.f16.f32 "
        "{%0,%1,%2,%3}, {%4,%5,%6,%7}, {%8,%9}, {%0,%1,%2,%3};\n"
        : "+f"(c[0]), "+f"(c[1]), "+f"(c[2]), "+f"(c[3])
        : "r"(a[0]), "r"(a[1]), "r"(a[2]), "r"(a[3]), "r"(b[0]), "r"(b[1]));
}
__device__ __forceinline__ void ldsm_x4(unsigned& r0, unsigned& r1,
                                        unsigned& r2, unsigned& r3,
                                        const void* p) {
    unsigned addr = (unsigned)__cvta_generic_to_shared(p);
    asm volatile("ldmatrix.sync.aligned.m8n8.x4.shared.b16 {%0,%1,%2,%3}, [%4];"
                 : "=r"(r0), "=r"(r1), "=r"(r2), "=r"(r3) : "r"(addr));
}
__device__ __forceinline__ void ldsm_x4_trans(unsigned& r0, unsigned& r1,
                                              unsigned& r2, unsigned& r3,
                                              const void* p) {
    unsigned addr = (unsigned)__cvta_generic_to_shared(p);
    asm volatile("ldmatrix.sync.aligned.m8n8.x4.trans.shared.b16 {%0,%1,%2,%3}, [%4];"
                 : "=r"(r0), "=r"(r1), "=r"(r2), "=r"(r3) : "r"(addr));
}
__device__ __forceinline__ unsigned h2u(__half2 h) { return *(unsigned*)&h; }

// ---------------------------------------------------------------------------
// Fused weight transposes (one launch)
// ---------------------------------------------------------------------------
__global__ void __launch_bounds__(256) trans_all_kernel(
    const float* __restrict__ wq, const float* __restrict__ wk,
    const float* __restrict__ wv, const float* __restrict__ wo,
    const float* __restrict__ w1, const float* __restrict__ w2)
{
    __shared__ float tile[32][33];
    const int bi = blockIdx.x;
    const float* src; __half* dst; int NS, K, n0, k0;
    if (bi < 3072) {
        const int m    = bi >> 10;
        const int r    = bi & 1023;
        const int head = r >> 6;
        const int tt   = r & 63;
        src = (m == 0 ? wq : (m == 1 ? wk : wv)) + (size_t)head * 1024 * 64;
        dst = (__half*)(g_scratch + OFF_WQKV) + m * MW + (size_t)head * 64 * 1024;
        NS = 64; K = 1024; n0 = (tt & 1) * 32; k0 = (tt >> 1) * 32;
    } else if (bi < 4096) {
        const int t = bi - 3072;
        src = wo; dst = (__half*)(g_scratch + OFF_WOC);
        NS = 1024; K = 1024; n0 = (t & 31) * 32; k0 = (t >> 5) * 32;
    } else if (bi < 8192) {
        const int t = bi - 4096;
        src = w1; dst = (__half*)(g_scratch + OFF_W1C);
        NS = 4096; K = 1024; n0 = (t & 127) * 32; k0 = (t >> 7) * 32;
    } else {
        const int t = bi - 8192;
        src = w2; dst = (__half*)(g_scratch + OFF_W2C);
        NS = 1024; K = 4096; n0 = (t & 31) * 32; k0 = (t >> 5) * 32;
    }
    const int tx = threadIdx.x, ty = threadIdx.y;
    #pragma unroll
    for (int i = 0; i < 32; i += 8)
        tile[ty + i][tx] = src[(size_t)(k0 + ty + i) * NS + n0 + tx];
    __syncthreads();
    #pragma unroll
    for (int i = 0; i < 32; i += 8)
        dst[(size_t)(n0 + ty + i) * K + k0 + tx] = __float2half_rn(tile[tx][ty + i]);
}

// ---------------------------------------------------------------------------
// LayerNorm: fp32 in -> fp16 out
// ---------------------------------------------------------------------------
__global__ void __launch_bounds__(256) ln_kernel(
    const float* __restrict__ xext, size_t xoff,
    const float* __restrict__ g, const float* __restrict__ be, size_t ooff)
{
    const float* x = rsrc(xext, xoff);
    __half* out = (__half*)(g_scratch + ooff);

    const int row = blockIdx.x;
    const int t   = threadIdx.x;
    const float4* xr = (const float4*)(x + (size_t)row * DD);
    float4 v = xr[t];

    float s = v.x + v.y + v.z + v.w;
    float q = v.x*v.x + v.y*v.y + v.z*v.z + v.w*v.w;
    #pragma unroll
    for (int o = 16; o; o >>= 1) {
        s += __shfl_xor_sync(0xffffffffu, s, o);
        q += __shfl_xor_sync(0xffffffffu, q, o);
    }
    __shared__ float ss[8], sq[8];
    if ((t & 31) == 0) { ss[t >> 5] = s; sq[t >> 5] = q; }
    __syncthreads();
    s = 0.f; q = 0.f;
    #pragma unroll
    for (int i = 0; i < 8; i++) { s += ss[i]; q += sq[i]; }

    const float mean = s * (1.0f / DD);
    const float var  = q * (1.0f / DD) - mean * mean;
    const float r    = rsqrtf(var + EPS);

    float4 gv = ((const float4*)g)[t];
    float4 bv = ((const float4*)be)[t];
    __half2 h0 = __floats2half2_rn((v.x - mean) * r * gv.x + bv.x,
                                   (v.y - mean) * r * gv.y + bv.y);
    __half2 h1 = __floats2half2_rn((v.z - mean) * r * gv.z + bv.z,
                                   (v.w - mean) * r * gv.w + bv.w);
    uint2 o; o.x = h2u(h0); o.y = h2u(h1);
    *(uint2*)(out + (size_t)row * DD + t * 4) = o;
}

// ---------------------------------------------------------------------------
// FP16 tensor-core GEMM (proven config): 128x128x32 CTA, 64x32 warp,
// 4-stage circular cp.async pipeline (80KB -> 2 CTAs/SM), ldmatrix fragments.
// ---------------------------------------------------------------------------
#define STG_H  ((size_t)(128 * 40 * 2))          // halves per stage (A+B)
#define HG_SMEM (4 * STG_H * 2)                  // bytes = 81920

template<bool BIAS, bool RELU, bool RESID, bool OUTH, bool SPLITN>
__global__ void __launch_bounds__(256, 2) hgemm_kernel(
    size_t aoff, size_t boff,
    const float* __restrict__ bias,
    const float* __restrict__ resid_ext, size_t resid_off,
    float* __restrict__ Cext, size_t coff,
    int M, int N, int K)
{
    extern __shared__ __half dsm[];
    const __half* A  = (const __half*)(g_scratch + aoff);
    const __half* Bt = (const __half*)(g_scratch + boff);
    const float* R = RESID ? rsrc(resid_ext, resid_off) : (const float*)nullptr;

    const int tid  = threadIdx.x;
    const int wid  = tid >> 5;
    const int lane = tid & 31;
    const int m0 = blockIdx.y * 128;
    const int n0 = blockIdx.x * 128;
    const int warp_m = (wid >> 2) * 64;
    const int warp_n = (wid & 3) * 32;
    const int g = lane >> 2;
    const int t = lane & 3;

    const int lm_row = (lane & 7) + ((lane >> 3) & 1) * 8;
    const int lm_col = (lane >> 4) * 8;
    const int lb_row = ((lane >> 4) * 8) + (lane & 7);
    const int lb_col = ((lane >> 3) & 1) * 8;

    float acc[4][4][4];
    #pragma unroll
    for (int mt = 0; mt < 4; mt++)
        #pragma unroll
        for (int nt = 0; nt < 4; nt++)
            #pragma unroll
            for (int r = 0; r < 4; r++) acc[mt][nt][r] = 0.f;

    const int nst = K >> 5;

    auto load_stage = [&](int s) {
        __half* sA = dsm + (size_t)(s & 3) * STG_H;
        __half* sB = sA + 128 * 40;
        const size_t kof = (size_t)s * 32;
        #pragma unroll
        for (int i = 0; i < 2; i++) {
            const int idx = tid + i * 256;
            const int r = idx >> 2;
            const int c = (idx & 3) << 3;
            cpa16(sA + r * 40 + c, A  + (size_t)(m0 + r) * K + kof + c);
            cpa16(sB + r * 40 + c, Bt + (size_t)(n0 + r) * K + kof + c);
        }
        cpa_commit();
    };

    load_stage(0);
    load_stage(1);
    load_stage(2);

    for (int s = 0; s < nst; s++) {
        if (s + 2 < nst) cpa_wait2(); else cpa_wait0();
        __syncthreads();
        const __half* sA = dsm + (size_t)(s & 3) * STG_H;
        const __half* sB = sA + 128 * 40;

        #pragma unroll
        for (int ks = 0; ks < 2; ks++) {
            unsigned af[4][4], bf[4][2];
            #pragma unroll
            for (int mt = 0; mt < 4; mt++)
                ldsm_x4(af[mt][0], af[mt][1], af[mt][2], af[mt][3],
                        sA + (warp_m + mt * 16 + lm_row) * 40 + ks * 16 + lm_col);
            #pragma unroll
            for (int np = 0; np < 2; np++)
                ldsm_x4(bf[2*np][0], bf[2*np][1], bf[2*np+1][0], bf[2*np+1][1],
                        sB + (warp_n + np * 16 + lb_row) * 40 + ks * 16 + lb_col);
            #pragma unroll
            for (int mt = 0; mt < 4; mt++)
                #pragma unroll
                for (int nt = 0; nt < 4; nt++)
                    mma_f16(acc[mt][nt], af[mt], bf[nt]);
        }

        if (s + 3 < nst) load_stage(s + 3);
    }

    #pragma unroll
    for (int mt = 0; mt < 4; mt++) {
        #pragma unroll
        for (int half_ = 0; half_ < 2; half_++) {
            const int gr = m0 + warp_m + mt * 16 + g + half_ * 8;
            const float* Rrow = RESID ? (R + (size_t)gr * N) : (const float*)nullptr;
            #pragma unroll
            for (int nt = 0; nt < 4; nt++) {
                const int gc = n0 + warp_n + nt * 8 + 2 * t;
                float v0 = acc[mt][nt][half_ * 2 + 0];
                float v1 = acc[mt][nt][half_ * 2 + 1];
                if (BIAS)  { v0 += bias[gc]; v1 += bias[gc + 1]; }
                if (RESID) { v0 += Rrow[gc]; v1 += Rrow[gc + 1]; }
                if (RELU)  { v0 = fmaxf(v0, 0.f); v1 = fmaxf(v1, 0.f); }
                if (SPLITN) {
                    __half* dst = (__half*)(g_scratch + coff + (size_t)(gc >> 10) * SEG);
                    *(__half2*)(dst + (size_t)gr * 1024 + (gc & 1023)) = __floats2half2_rn(v0, v1);
                } else if (OUTH) {
                    __half* Crow = (__half*)(g_scratch + coff) + (size_t)gr * N;
                    *(__half2*)(Crow + gc) = __floats2half2_rn(v0, v1);
                } else {
                    float* Crow = (Cext ? Cext : (g_scratch + coff)) + (size_t)gr * N;
                    *(float2*)(Crow + gc) = make_float2(v0, v1);
                }
            }
        }
    }
}

// ---------------------------------------------------------------------------
// FP16 tensor-core causal flash attention: 64x64 tiles, 128 threads.
// exp2-domain softmax (log2e folded into Q scale, bare exp2f on MUFU).
// Per-thread partial l accumulation; quad reduction deferred to epilogue.
// ---------------------------------------------------------------------------
__global__ void __launch_bounds__(128) attn_kernel()
{
    __shared__ __half Ks[2][64][72];
    __shared__ __half Vs[2][64][72];

    const __half* qh = (const __half*)(g_scratch + OFF_Q);
    const __half* kh = (const __half*)(g_scratch + OFF_K);
    const __half* vh = (const __half*)(g_scratch + OFF_V);
    __half* ctx      = (__half*)(g_scratch + OFF_CTX);

    const int qt   = (int)(gridDim.x - 1) - (int)blockIdx.x;   // reversed (LPT)
    const int head = blockIdx.y;
    const int b    = blockIdx.z;
    const int tid  = threadIdx.x;
    const int w    = tid >> 5;
    const int lane = tid & 31;
    const int g    = lane >> 2;
    const int t    = lane & 3;

    const int lb_row = ((lane >> 4) * 8) + (lane & 7);
    const int lb_col = ((lane >> 3) & 1) * 8;

    const int q0 = qt * 64;
    const size_t headoff = (size_t)head * 64;
    const size_t rowbase = (size_t)b * TT;

    auto issueKV = [&](int kt2, int bf) {
        const size_t kbase = (rowbase + (size_t)kt2 * 64) * DD + headoff;
        #pragma unroll
        for (int j = 0; j < 4; j++) {
            const int idx = tid + j * 128;
            const int row = idx >> 3;
            const int c   = (idx & 7) << 3;
            cpa16(&Ks[bf][row][c], kh + kbase + (size_t)row * DD + c);
            cpa16(&Vs[bf][row][c], vh + kbase + (size_t)row * DD + c);
        }
        cpa_commit();
    };

    issueKV(0, 0);

    // Q fragments from global, scaled by (1/8)*log2(e): S ends up in log2 units.
    unsigned Qf[4][4];
    {
        const __half2 sc = __floats2half2_rn(0.18033688f, 0.18033688f);  // 0.125*log2e
        const size_t r0 = (rowbase + q0 + 16*w + g) * DD + headoff;
        const size_t r1 = r0 + 8 * DD;
        #pragma unroll
        for (int ks = 0; ks < 4; ks++) {
            const int e = ks * 16 + 2 * t;
            __half2 a0 = *(const __half2*)(qh + r0 + e);
            __half2 a1 = *(const __half2*)(qh + r1 + e);
            __half2 a2 = *(const __half2*)(qh + r0 + e + 8);
            __half2 a3 = *(const __half2*)(qh + r1 + e + 8);
            Qf[ks][0] = h2u(__hmul2(a0, sc));
            Qf[ks][1] = h2u(__hmul2(a1, sc));
            Qf[ks][2] = h2u(__hmul2(a2, sc));
            Qf[ks][3] = h2u(__hmul2(a3, sc));
        }
    }

    float Oacc[8][4];
    #pragma unroll
    for (int nt = 0; nt < 8; nt++)
        #pragma unroll
        for (int r = 0; r < 4; r++) Oacc[nt][r] = 0.f;
    float m0 = -1e30f, m1 = -1e30f, l0 = 0.f, l1 = 0.f;   // l = per-thread partial

    const int nkt = qt + 1;

    for (int kt = 0; kt < nkt; kt++) {
        const int buf = kt & 1;
        cpa_wait0();
        __syncthreads();
        if (kt + 1 < nkt) issueKV(kt + 1, buf ^ 1);

        // ---- S = Q K^T (64 x 64), log2 units ----
        float S[8][4];
        #pragma unroll
        for (int nt = 0; nt < 8; nt++)
            #pragma unroll
            for (int r = 0; r < 4; r++) S[nt][r] = 0.f;

        #pragma unroll
        for (int ks = 0; ks < 4; ks++) {
            unsigned bfrag[8][2];
            #pragma unroll
            for (int np = 0; np < 4; np++) {
                ldsm_x4(bfrag[2*np][0], bfrag[2*np][1], bfrag[2*np+1][0], bfrag[2*np+1][1],
                        &Ks[buf][np * 16 + lb_row][ks * 16 + lb_col]);
            }
            #pragma unroll
            for (int nt = 0; nt < 8; nt++)
                mma_f16(S[nt], Qf[ks], bfrag[nt]);
        }

        // ---- mask + online softmax (base-2) ----
        const int qrow0 = q0 + 16*w + g;
        const int qrow1 = qrow0 + 8;
        if (kt == qt) {
            const int ktbase = kt * 64;
            #pragma unroll
            for (int nt = 0; nt < 8; nt++) {
                const int key = ktbase + nt*8 + 2*t;
                if (key     > qrow0) S[nt][0] = -1e30f;
                if (key + 1 > qrow0) S[nt][1] = -1e30f;
                if (key     > qrow1) S[nt][2] = -1e30f;
                if (key + 1 > qrow1) S[nt][3] = -1e30f;
            }
        }
        float mn0 = m0, mn1 = m1;
        #pragma unroll
        for (int nt = 0; nt < 8; nt++) {
            mn0 = fmaxf(mn0, fmaxf(S[nt][0], S[nt][1]));
            mn1 = fmaxf(mn1, fmaxf(S[nt][2], S[nt][3]));
        }
        mn0 = fmaxf(mn0, __shfl_xor_sync(0xffffffffu, mn0, 1));
        mn0 = fmaxf(mn0, __shfl_xor_sync(0xffffffffu, mn0, 2));
        mn1 = fmaxf(mn1, __shfl_xor_sync(0xffffffffu, mn1, 1));
        mn1 = fmaxf(mn1, __shfl_xor_sync(0xffffffffu, mn1, 2));

        const float corr0 = exp2f(m0 - mn0);
        const float corr1 = exp2f(m1 - mn1);
        m0 = mn0; m1 = mn1;

        // P in registers; per-thread partial l from fp32 exp2s
        unsigned Pa[8][2];
        float ls0 = 0.f, ls1 = 0.f;
        #pragma unroll
        for (int nt = 0; nt < 8; nt++) {
            float e0 = exp2f(S[nt][0] - m0);
            float e1 = exp2f(S[nt][1] - m0);
            float e2 = exp2f(S[nt][2] - m1);
            float e3 = exp2f(S[nt][3] - m1);
            ls0 += e0 + e1;
            ls1 += e2 + e3;
            Pa[nt][0] = h2u(__floats2half2_rn(e0, e1));
            Pa[nt][1] = h2u(__floats2half2_rn(e2, e3));
        }
        l0 = l0 * corr0 + ls0;
        l1 = l1 * corr1 + ls1;

        #pragma unroll
        for (int nt = 0; nt < 8; nt++) {
            Oacc[nt][0] *= corr0; Oacc[nt][1] *= corr0;
            Oacc[nt][2] *= corr1; Oacc[nt][3] *= corr1;
        }

        // ---- O += P V (64 x 64, k=64) ----
        #pragma unroll
        for (int ks = 0; ks < 4; ks++) {
            unsigned af[4];
            af[0] = Pa[2*ks    ][0];
            af[1] = Pa[2*ks    ][1];
            af[2] = Pa[2*ks + 1][0];
            af[3] = Pa[2*ks + 1][1];
            #pragma unroll
            for (int np = 0; np < 4; np++) {
                const int vrow = ks * 16 + (lane & 7) + ((lane >> 3) & 1) * 8;
                const int vcol = 8 * (2 * np + (lane >> 4));
                unsigned b0, b1, b2, b3;
                ldsm_x4_trans(b0, b1, b2, b3, &Vs[buf][vrow][vcol]);
                unsigned bf0[2] = {b0, b1};
                unsigned bf1[2] = {b2, b3};
                mma_f16(Oacc[2*np    ], af, bf0);
                mma_f16(Oacc[2*np + 1], af, bf1);
            }
        }
    }

    // ---- epilogue: quad-reduce l, normalize, store fp16 ctx ----
    l0 += __shfl_xor_sync(0xffffffffu, l0, 1);
    l0 += __shfl_xor_sync(0xffffffffu, l0, 2);
    l1 += __shfl_xor_sync(0xffffffffu, l1, 1);
    l1 += __shfl_xor_sync(0xffffffffu, l1, 2);
    const float inv0 = 1.f / l0;
    const float inv1 = 1.f / l1;
    __half* base0 = ctx + (rowbase + q0 + 16*w + g    ) * DD + headoff;
    __half* base1 = ctx + (rowbase + q0 + 16*w + g + 8) * DD + headoff;
    #pragma unroll
    for (int nt = 0; nt < 8; nt++) {
        const int col = nt*8 + 2*t;
        *(__half2*)(base0 + col) = __floats2half2_rn(Oacc[nt][0] * inv0, Oacc[nt][1] * inv0);
        *(__half2*)(base1 + col) = __floats2half2_rn(Oacc[nt][2] * inv1, Oacc[nt][3] * inv1);
    }
}

// ---------------------------------------------------------------------------
// Launch
// ---------------------------------------------------------------------------
extern "C" void kernel_launch(void* const* d_in, const int* in_sizes, int n_in,
                              void* d_out, int out_size)
{
    const float* x   = (const float*)d_in[0];
    const float* Wq  = (const float*)d_in[1];
    const float* Wk  = (const float*)d_in[2];
    const float* Wv  = (const float*)d_in[3];
    const float* Wo  = (const float*)d_in[4];
    const float* bo  = (const float*)d_in[5];
    const float* W1  = (const float*)d_in[6];
    const float* b1  = (const float*)d_in[7];
    const float* W2  = (const float*)d_in[8];
    const float* b2  = (const float*)d_in[9];
    const float* g1  = (const float*)d_in[10];
    const float* be1 = (const float*)d_in[11];
    const float* g2  = (const float*)d_in[12];
    const float* be2 = (const float*)d_in[13];
    float* out = (float*)d_out;

    // Opt-in dynamic SMEM
    cudaFuncSetAttribute(hgemm_kernel<false,false,false,true,true>,
                         cudaFuncAttributeMaxDynamicSharedMemorySize, HG_SMEM);
    cudaFuncSetAttribute(hgemm_kernel<true,false,true,false,false>,
                         cudaFuncAttributeMaxDynamicSharedMemorySize, HG_SMEM);
    cudaFuncSetAttribute(hgemm_kernel<true,true,false,true,false>,
                         cudaFuncAttributeMaxDynamicSharedMemorySize, HG_SMEM);

    // 0) ALL weight transposes in one launch
    trans_all_kernel<<<12288, dim3(32, 8)>>>(Wq, Wk, Wv, Wo, W1, W2);

    // 1) LN1: x -> h (fp16)
    ln_kernel<<<NROWS, 256>>>(x, 0, g1, be1, OFF_H);

    // 2) Fused QKV projection (N = 3072; outputs split into q/k/v fp16)
    hgemm_kernel<false,false,false,true,true>
        <<<dim3(3072/128, NROWS/128), 256, HG_SMEM>>>(
        OFF_H, OFF_WQKV, nullptr, nullptr, 0, nullptr, OFF_Q, NROWS, 3072, DD);

    // 3) FP16 tensor-core causal flash attention -> ctx (fp16)
    attn_kernel<<<dim3(TT / 64, HH, BB), 128>>>();

    // 4) Output projection + bias + residual(x): ctx -> x2 (fp32)
    dim3 gq(DD / 128, NROWS / 128);
    hgemm_kernel<true,false,true,false,false><<<gq, 256, HG_SMEM>>>(
        OFF_CTX, OFF_WOC, bo, x, 0, nullptr, OFF_X2, NROWS, DD, DD);

    // 5) LN2: x2 -> h (fp16)
    ln_kernel<<<NROWS, 256>>>(nullptr, OFF_X2, g2, be2, OFF_H);

    // 6) FFN1 (+bias, relu): h -> ff (fp16)
    hgemm_kernel<true,true,false,true,false>
        <<<dim3(DFF / 128, NROWS / 128), 256, HG_SMEM>>>(
        OFF_H, OFF_W1C, b1, nullptr, 0, nullptr, OFF_FF, NROWS, DFF, DD);

    // 7) FFN2 (+bias, +residual x2) -> final output (fp32)
    hgemm_kernel<true,false,true,false,false><<<gq, 256, HG_SMEM>>>(
        OFF_FF, OFF_W2C, b2, nullptr, OFF_X2, out, 0, NROWS, DD, DFF);
}